// round 4
// baseline (speedup 1.0000x reference)
#include <cuda_runtime.h>
#include <cuda_bf16.h>

#define BAGS 16
#define NN   5000
#define EE   160000
#define DENC 256

// ---------------- scratch (device globals; no allocation allowed) -----------
__device__ float g_h  [BAGS * NN * DENC];   // encoder output / later g2
__device__ float g_g1 [BAGS * NN * DENC];   // layer-1 output
__device__ float g_agg[BAGS * NN * DENC];   // mean-aggregated features
__device__ float g_emb[BAGS * DENC];        // pooled embedding
__device__ int   g_deg   [BAGS * NN];
__device__ int   g_rowptr[BAGS * (NN + 1)];
__device__ int   g_cursor[BAGS * NN];
__device__ int   g_col   [BAGS * EE];

// compile-time scratch-buffer selector (no host-side symbol lookups)
#define BUF_H   0
#define BUF_G1  1
#define BUF_AGG 2
template <int ID> __device__ __forceinline__ float* buf() {
    if (ID == BUF_H)  return g_h;
    if (ID == BUF_G1) return g_g1;
    return g_agg;
}

// ---------------- small utility kernels -------------------------------------
__global__ void k_zero() {
    int i = blockIdx.x * blockDim.x + threadIdx.x;
    if (i < BAGS * NN)   g_deg[i] = 0;
    if (i < BAGS * DENC) g_emb[i] = 0.f;
}

// edge_index is int32 (JAX x64-disabled downgrades the requested int64)
__global__ void k_deg(const int* __restrict__ ei) {
    int e = blockIdx.x * blockDim.x + threadIdx.x;
    int b = blockIdx.y;
    if (e >= EE) return;
    int dst = ei[(size_t)b * 2 * EE + EE + e];
    if ((unsigned)dst >= NN) return;           // insurance vs. dtype surprises
    atomicAdd(&g_deg[b * NN + dst], 1);
}

// one block per bag, 1024 threads: exclusive scan of deg -> rowptr, cursor
__global__ void k_scan() {
    int b = blockIdx.x, t = threadIdx.x;
    __shared__ int sh[1024];
    int carry = 0;
    for (int c = 0; c < 5; c++) {
        int idx = c * 1024 + t;
        int v = (idx < NN) ? g_deg[b * NN + idx] : 0;
        sh[t] = v;
        __syncthreads();
        for (int off = 1; off < 1024; off <<= 1) {
            int add = (t >= off) ? sh[t - off] : 0;
            __syncthreads();
            sh[t] += add;
            __syncthreads();
        }
        int excl = sh[t] - v;
        if (idx < NN) {
            int rp = carry + excl;
            g_rowptr[b * (NN + 1) + idx] = rp;
            g_cursor[b * NN + idx] = rp;
        }
        int tot = sh[1023];
        __syncthreads();
        carry += tot;
    }
    if (t == 0) g_rowptr[b * (NN + 1) + NN] = carry;
}

__global__ void k_fill(const int* __restrict__ ei) {
    int e = blockIdx.x * blockDim.x + threadIdx.x;
    int b = blockIdx.y;
    if (e >= EE) return;
    int src = ei[(size_t)b * 2 * EE + e];
    int dst = ei[(size_t)b * 2 * EE + EE + e];
    if ((unsigned)dst >= NN || (unsigned)src >= NN) return;
    int p = atomicAdd(&g_cursor[b * NN + dst], 1);
    g_col[b * EE + p] = src;
}

// ---------------- mean aggregation: one warp per node ------------------------
template <int SRC, int DST>
__global__ void k_agg() {
    const float* __restrict__ X = buf<SRC>();
    float* __restrict__ O = buf<DST>();
    int w = (blockIdx.x * blockDim.x + threadIdx.x) >> 5;
    int lane = threadIdx.x & 31;
    if (w >= BAGS * NN) return;
    int b = w / NN, i = w - b * NN;
    int r0 = g_rowptr[b * (NN + 1) + i];
    int r1 = g_rowptr[b * (NN + 1) + i + 1];
    const float* Xb   = X + (size_t)b * NN * DENC;
    const int*   colb = g_col + b * EE;
    float4 a0 = make_float4(0.f, 0.f, 0.f, 0.f);
    float4 a1 = make_float4(0.f, 0.f, 0.f, 0.f);
    for (int e = r0; e < r1; e++) {
        int s = __ldg(&colb[e]);
        const float4* row = (const float4*)(Xb + (size_t)s * DENC);
        float4 v0 = __ldg(&row[lane]);
        float4 v1 = __ldg(&row[lane + 32]);
        a0.x += v0.x; a0.y += v0.y; a0.z += v0.z; a0.w += v0.w;
        a1.x += v1.x; a1.y += v1.y; a1.z += v1.z; a1.w += v1.w;
    }
    int d = r1 - r0;
    float inv = 1.f / (float)(d > 1 ? d : 1);
    a0.x *= inv; a0.y *= inv; a0.z *= inv; a0.w *= inv;
    a1.x *= inv; a1.y *= inv; a1.z *= inv; a1.w *= inv;
    float4* orow = (float4*)(O + (size_t)(b * NN + i) * DENC);
    orow[lane] = a0;
    orow[lane + 32] = a1;
}

// ---------------- tiled SGEMM: C = relu(A1@W1 [+ A2@W2] + bias) -------------
// BM=64 BN=64 BK=16, 256 threads, 4x4 per thread. N fixed 256, M = NN.
// SRC1/SRC2/DST select scratch buffers; SRC1 == -1 means external pointer Aext.
template <int K1, bool DUAL, int SRC1, int SRC2, int DST>
__global__ void k_gemm(const float* __restrict__ Aext,
                       const float* __restrict__ W1, const float* __restrict__ W2,
                       const float* __restrict__ bias) {
    const int M = NN, Nc = DENC;
    int b = blockIdx.z;
    int row0 = blockIdx.y * 64, col0 = blockIdx.x * 64;
    int tid = threadIdx.x;
    int tx = tid & 15, ty = tid >> 4;

    __shared__ float As[16][64];
    __shared__ float Ws[16][64];
    float acc[4][4] = {};

    int lm = tid >> 2;            // 0..63 : A row within tile
    int lk = (tid & 3) * 4;       // 0,4,8,12 : A k-quad
    int wk = tid >> 4;            // 0..15 : W k within tile
    int wn = (tid & 15) * 4;      // W n-quad
    int row = row0 + lm;
    bool rv = row < M;

    #pragma unroll
    for (int pass = 0; pass < (DUAL ? 2 : 1); pass++) {
        const float* Abase = (pass == 0)
            ? (SRC1 < 0 ? Aext : buf<(SRC1 < 0 ? 0 : SRC1)>())
            : buf<(SRC2 < 0 ? 0 : SRC2)>();
        const float* A = Abase + (size_t)b * M * K1;
        const float* W = (pass == 0 ? W1 : W2);
        for (int k0 = 0; k0 < K1; k0 += 16) {
            float4 av = rv ? *(const float4*)(A + (size_t)row * K1 + k0 + lk)
                           : make_float4(0.f, 0.f, 0.f, 0.f);
            float4 wv = *(const float4*)(W + (size_t)(k0 + wk) * Nc + col0 + wn);
            __syncthreads();
            As[lk + 0][lm] = av.x; As[lk + 1][lm] = av.y;
            As[lk + 2][lm] = av.z; As[lk + 3][lm] = av.w;
            *(float4*)&Ws[wk][wn] = wv;
            __syncthreads();
            #pragma unroll
            for (int k = 0; k < 16; k++) {
                float4 a = *(float4*)&As[k][ty * 4];
                float4 w = *(float4*)&Ws[k][tx * 4];
                float ar[4] = {a.x, a.y, a.z, a.w};
                float wr[4] = {w.x, w.y, w.z, w.w};
                #pragma unroll
                for (int i = 0; i < 4; i++)
                    #pragma unroll
                    for (int j = 0; j < 4; j++)
                        acc[i][j] += ar[i] * wr[j];
            }
        }
    }

    int orow = row0 + ty * 4, ocol = col0 + tx * 4;
    float4 bv = *(const float4*)(bias + ocol);
    float bb[4] = {bv.x, bv.y, bv.z, bv.w};
    float* Cb = buf<DST>() + (size_t)b * M * Nc;
    #pragma unroll
    for (int i = 0; i < 4; i++) {
        if (orow + i < M) {
            float4 r;
            r.x = fmaxf(acc[i][0] + bb[0], 0.f);
            r.y = fmaxf(acc[i][1] + bb[1], 0.f);
            r.z = fmaxf(acc[i][2] + bb[2], 0.f);
            r.w = fmaxf(acc[i][3] + bb[3], 0.f);
            *(float4*)(Cb + (size_t)(orow + i) * Nc + ocol) = r;
        }
    }
}

// ---------------- emb[b][c] = sum_i g2[b][i][c]  (g2 lives in g_h) -----------
__global__ void k_reduce() {
    int b = blockIdx.y, c = threadIdx.x;
    int i0 = blockIdx.x * 250, i1 = i0 + 250;
    const float* Gb = g_h + (size_t)b * NN * DENC;
    float s = 0.f;
    for (int i = i0; i < i1; i++) s += Gb[(size_t)i * DENC + c];
    atomicAdd(&g_emb[b * DENC + c], s);
}

// ---------------- classifier: out = relu(emb@Wc1+bc1)@Wc2 + bc2 -------------
__global__ void k_cls(const float* __restrict__ Wc1, const float* __restrict__ bc1,
                      const float* __restrict__ Wc2, const float* __restrict__ bc2,
                      float* __restrict__ out) {
    int b = blockIdx.x, t = threadIdx.x;   // 128 threads
    __shared__ float es[256];
    __shared__ float r0[128], r1[128];
    es[t]       = g_emb[b * DENC + t];
    es[t + 128] = g_emb[b * DENC + t + 128];
    __syncthreads();
    float a = bc1[t];
    #pragma unroll 8
    for (int k = 0; k < 256; k++) a += es[k] * Wc1[k * 128 + t];
    float h1 = fmaxf(a, 0.f);
    r0[t] = h1 * Wc2[t * 2 + 0];
    r1[t] = h1 * Wc2[t * 2 + 1];
    __syncthreads();
    for (int off = 64; off > 0; off >>= 1) {
        if (t < off) { r0[t] += r0[t + off]; r1[t] += r1[t + off]; }
        __syncthreads();
    }
    if (t == 0) {
        out[b * 2 + 0] = r0[0] + bc2[0];
        out[b * 2 + 1] = r1[0] + bc2[1];
    }
}

// ---------------- launch ------------------------------------------------------
extern "C" void kernel_launch(void* const* d_in, const int* in_sizes, int n_in,
                              void* d_out, int out_size) {
    (void)in_sizes; (void)n_in; (void)out_size;
    const float* x   = (const float*)d_in[0];
    const int*   ei  = (const int*)d_in[1];       // int32! (JAX x64 disabled)
    const float* We  = (const float*)d_in[2];
    const float* be  = (const float*)d_in[3];
    const float* Wl1 = (const float*)d_in[4];
    const float* bl1 = (const float*)d_in[5];
    const float* Wr1 = (const float*)d_in[6];
    const float* Wl2 = (const float*)d_in[7];
    const float* bl2 = (const float*)d_in[8];
    const float* Wr2 = (const float*)d_in[9];
    // d_in[10..12] (Wlp, blp, Wrp) are dead: softmax over a size-1 axis == 1
    const float* Wc1 = (const float*)d_in[13];
    const float* bc1 = (const float*)d_in[14];
    const float* Wc2 = (const float*)d_in[15];
    const float* bc2 = (const float*)d_in[16];
    float* out = (float*)d_out;

    dim3 gemm_grid(DENC / 64, (NN + 63) / 64, BAGS);     // (4, 79, 16)
    dim3 edge_grid((EE + 255) / 256, BAGS);

    // zero deg + emb
    k_zero<<<(BAGS * NN + 255) / 256, 256>>>();
    // encoder: h = relu(x @ We + be)
    k_gemm<128, false, -1, -1, BUF_H><<<gemm_grid, 256>>>(x, We, nullptr, be);
    // CSR build
    k_deg<<<edge_grid, 256>>>(ei);
    k_scan<<<BAGS, 1024>>>();
    k_fill<<<edge_grid, 256>>>(ei);
    // layer 1: g1 = relu(agg(h)@Wl1 + h@Wr1 + bl1)
    k_agg<BUF_H, BUF_AGG><<<(BAGS * NN) / 8, 256>>>();
    k_gemm<256, true, BUF_AGG, BUF_H, BUF_G1><<<gemm_grid, 256>>>(nullptr, Wl1, Wr1, bl1);
    // layer 2: g2 = relu(agg(g1)@Wl2 + g1@Wr2 + bl2)   (g2 -> g_h, free now)
    k_agg<BUF_G1, BUF_AGG><<<(BAGS * NN) / 8, 256>>>();
    k_gemm<256, true, BUF_AGG, BUF_G1, BUF_H><<<gemm_grid, 256>>>(nullptr, Wl2, Wr2, bl2);
    // pooled embedding: emb = column-sum of g2 (softmax over 1 cluster == 1)
    k_reduce<<<dim3(20, BAGS), 256>>>();
    // classifier
    k_cls<<<BAGS, 128>>>(Wc1, bc1, Wc2, bc2, out);
}

// round 6
// speedup vs baseline: 1.3630x; 1.3630x over previous
#include <cuda_runtime.h>
#include <cuda_bf16.h>
#include <cstdint>

#define BAGS 16
#define NN   5000
#define EE   160000
#define DE   256
#define DIN  128

// ---------------- scratch (device globals) -----------------------------------
__device__ __align__(16) __nv_bfloat16 g_xh[BAGS*NN*DIN], g_xl[BAGS*NN*DIN];
__device__ __align__(16) __nv_bfloat16 g_hh[BAGS*NN*DE],  g_hl[BAGS*NN*DE];   // h, later g1
__device__ __align__(16) float g_u [BAGS*NN*DE];
__device__ __align__(16) float g_v [BAGS*NN*DE];
__device__ __align__(16) float g_g2[BAGS*NN*DE];
__device__ float g_emb[BAGS*DE];
// transposed split weights:  Wt[n][k] = W[k][n]
__device__ __align__(16) __nv_bfloat16 g_weth[DE*DIN], g_wetl[DE*DIN];
__device__ __align__(16) __nv_bfloat16 g_w1h[DE*DE], g_w1l[DE*DE];   // Wl1^T
__device__ __align__(16) __nv_bfloat16 g_w2h[DE*DE], g_w2l[DE*DE];   // Wr1^T
__device__ __align__(16) __nv_bfloat16 g_w3h[DE*DE], g_w3l[DE*DE];   // Wl2^T
__device__ __align__(16) __nv_bfloat16 g_w4h[DE*DE], g_w4l[DE*DE];   // Wr2^T
// CSR
__device__ int g_deg[BAGS*NN], g_rowptr[BAGS*(NN+1)], g_cursor[BAGS*NN], g_col[BAGS*EE];

// ---------------- helpers -----------------------------------------------------
__device__ __forceinline__ uint32_t smem_u32(const void* p) {
    uint32_t a;
    asm("{ .reg .u64 t; cvta.to.shared.u64 t, %1; cvt.u32.u64 %0, t; }" : "=r"(a) : "l"(p));
    return a;
}
__device__ __forceinline__ void split_pack(float v0, float v1, uint32_t& hp, uint32_t& lp) {
    __nv_bfloat16 h0 = __float2bfloat16(v0), h1 = __float2bfloat16(v1);
    __nv_bfloat16 l0 = __float2bfloat16(v0 - __bfloat162float(h0));
    __nv_bfloat16 l1 = __float2bfloat16(v1 - __bfloat162float(h1));
    hp = (uint32_t)__bfloat16_as_ushort(h0) | ((uint32_t)__bfloat16_as_ushort(h1) << 16);
    lp = (uint32_t)__bfloat16_as_ushort(l0) | ((uint32_t)__bfloat16_as_ushort(l1) << 16);
}

// selectors
template <int S> __device__ __forceinline__ const __nv_bfloat16* apair(int lo) {
    if (S == 0) return lo ? g_xl : g_xh;
    return lo ? g_hl : g_hh;
}
template <int S> __device__ __forceinline__ __nv_bfloat16* wpair(int lo) {
    switch (S) {
        case 0:  return lo ? g_wetl : g_weth;
        case 1:  return lo ? g_w1l : g_w1h;
        case 2:  return lo ? g_w2l : g_w2h;
        case 3:  return lo ? g_w3l : g_w3h;
        default: return lo ? g_w4l : g_w4h;
    }
}

// ---------------- prep kernels ------------------------------------------------
__global__ void k_zero() {
    int i = blockIdx.x * blockDim.x + threadIdx.x;
    if (i < BAGS * NN) g_deg[i] = 0;
    if (i < BAGS * DE) g_emb[i] = 0.f;
}
__global__ void k_cvtx(const float* __restrict__ x) {
    int i = blockIdx.x * blockDim.x + threadIdx.x;
    if (i >= BAGS * NN * DIN) return;
    float v = x[i];
    __nv_bfloat16 h = __float2bfloat16(v);
    g_xh[i] = h;
    g_xl[i] = __float2bfloat16(v - __bfloat162float(h));
}
template <int WSEL, int K>
__global__ void k_cvtw(const float* __restrict__ W) {
    int i = blockIdx.x * blockDim.x + threadIdx.x;
    if (i >= 256 * K) return;
    int n = i / K, k = i - n * K;
    float v = W[k * 256 + n];
    __nv_bfloat16 h = __float2bfloat16(v);
    wpair<WSEL>(0)[i] = h;
    wpair<WSEL>(1)[i] = __float2bfloat16(v - __bfloat162float(h));
}

// ---------------- CSR build ---------------------------------------------------
__global__ void k_deg(const int* __restrict__ ei) {
    int e = blockIdx.x * blockDim.x + threadIdx.x;
    int b = blockIdx.y;
    if (e >= EE) return;
    int dst = ei[(size_t)b * 2 * EE + EE + e];
    if ((unsigned)dst >= NN) return;
    atomicAdd(&g_deg[b * NN + dst], 1);
}
__global__ void k_scan() {
    int b = blockIdx.x, t = threadIdx.x;
    __shared__ int sh[1024];
    int carry = 0;
    for (int c = 0; c < 5; c++) {
        int idx = c * 1024 + t;
        int v = (idx < NN) ? g_deg[b * NN + idx] : 0;
        sh[t] = v;
        __syncthreads();
        for (int off = 1; off < 1024; off <<= 1) {
            int add = (t >= off) ? sh[t - off] : 0;
            __syncthreads();
            sh[t] += add;
            __syncthreads();
        }
        int excl = sh[t] - v;
        if (idx < NN) {
            g_rowptr[b * (NN + 1) + idx] = carry + excl;
            g_cursor[b * NN + idx] = carry + excl;
        }
        int tot = sh[1023];
        __syncthreads();
        carry += tot;
    }
    if (t == 0) g_rowptr[b * (NN + 1) + NN] = carry;
}
__global__ void k_fill(const int* __restrict__ ei) {
    int e = blockIdx.x * blockDim.x + threadIdx.x;
    int b = blockIdx.y;
    if (e >= EE) return;
    int src = ei[(size_t)b * 2 * EE + e];
    int dst = ei[(size_t)b * 2 * EE + EE + e];
    if ((unsigned)dst >= NN || (unsigned)src >= NN) return;
    int p = atomicAdd(&g_cursor[b * NN + dst], 1);
    g_col[b * EE + p] = src;
}

// ---------------- HMMA GEMM  C[m,n] = sum_k A[m,k] * Wt[n,k] ------------------
// BM=128, BN=128, BK=32, 256 threads (8 warps, 2x4), warp tile 64x32.
// 3 precision passes: AhBh, AhBl, AlBh accumulated in fp32.
// Smem rows padded to 80B for conflict-free 32-bit fragment loads.
#define PITCH 80

__device__ __forceinline__ void issue_chunk(
    const __nv_bfloat16* __restrict__ Agl, const __nv_bfloat16* __restrict__ Bgl,
    int KD, int m0, int kc, char* sA, char* sB, int tid)
{
    #pragma unroll
    for (int v = 0; v < 2; v++) {
        int idx = v * 256 + tid;
        int row = idx >> 2, c16 = idx & 3;
        int gr = m0 + row;
        const void* src = Agl + (size_t)gr * KD + kc + c16 * 8;
        uint32_t dst = smem_u32(sA + row * PITCH + c16 * 16);
        int sz = (gr < NN) ? 16 : 0;
        asm volatile("cp.async.cg.shared.global [%0], [%1], 16, %2;"
                     :: "r"(dst), "l"(src), "r"(sz));
    }
    #pragma unroll
    for (int v = 0; v < 2; v++) {
        int idx = v * 256 + tid;
        int row = idx >> 2, c16 = idx & 3;
        const void* src = Bgl + (size_t)row * KD + kc + c16 * 8;
        uint32_t dst = smem_u32(sB + row * PITCH + c16 * 16);
        asm volatile("cp.async.cg.shared.global [%0], [%1], 16;"
                     :: "r"(dst), "l"(src));
    }
    asm volatile("cp.async.commit_group;");
}

// EPI 0: fp32 out (+bias if HASB) into U (OSEL=1) or V (OSEL=2)
// EPI 1: relu(acc+bias) -> split bf16 pair into g_hh/g_hl
template <int KD, int ASEL, int WSEL, int OSEL, int EPI, bool HASB>
__global__ void __launch_bounds__(256, 1) k_mma(const float* __restrict__ bias) {
    __shared__ __align__(16) char smA[2][128 * PITCH];
    __shared__ __align__(16) char smB[2][128 * PITCH];

    int tid = threadIdx.x, lane = tid & 31, warp = tid >> 5;
    int wm = warp & 1, wn = warp >> 1;               // 2 x 4 warp grid
    int m0 = blockIdx.x * 128, n0 = blockIdx.y * 128, b = blockIdx.z;

    const __nv_bfloat16* Ah = apair<ASEL>(0) + (size_t)b * NN * KD;
    const __nv_bfloat16* Al = apair<ASEL>(1) + (size_t)b * NN * KD;
    const __nv_bfloat16* Bh = wpair<WSEL>(0) + (size_t)n0 * KD;
    const __nv_bfloat16* Bl = wpair<WSEL>(1) + (size_t)n0 * KD;

    const int NCH = KD / 32, TOT = 3 * NCH;
    float acc[4][4][4] = {};

    // pass p: A = (p==2 ? Al : Ah), B = (p==1 ? Bl : Bh)
    #define AP(p) ((p) == 2 ? Al : Ah)
    #define BP(p) ((p) == 1 ? Bl : Bh)
    #define ISSUE(it) do { int _p = (it) / NCH, _c = (it) % NCH;                     \
        issue_chunk(AP(_p), BP(_p), KD, m0, _c * 32,                                 \
                    smA[(it) & 1], smB[(it) & 1], tid); } while (0)

    ISSUE(0);
    ISSUE(1);

    for (int it = 0; it < TOT; it++) {
        if (it + 1 < TOT) asm volatile("cp.async.wait_group 1;");
        else              asm volatile("cp.async.wait_group 0;");
        __syncthreads();

        const char* sA = smA[it & 1];
        const char* sB = smB[it & 1];
        #pragma unroll
        for (int ks = 0; ks < 2; ks++) {
            int kk = ks * 16 + (lane & 3) * 2;
            uint32_t afr[4][4];
            #pragma unroll
            for (int mi = 0; mi < 4; mi++) {
                const char* base = sA + (wm * 64 + mi * 16 + (lane >> 2)) * PITCH + kk * 2;
                afr[mi][0] = *(const uint32_t*)(base);
                afr[mi][1] = *(const uint32_t*)(base + 8 * PITCH);
                afr[mi][2] = *(const uint32_t*)(base + 16);
                afr[mi][3] = *(const uint32_t*)(base + 8 * PITCH + 16);
            }
            uint32_t bfr[4][2];
            #pragma unroll
            for (int ni = 0; ni < 4; ni++) {
                const char* base = sB + (wn * 32 + ni * 8 + (lane >> 2)) * PITCH + kk * 2;
                bfr[ni][0] = *(const uint32_t*)(base);
                bfr[ni][1] = *(const uint32_t*)(base + 16);
            }
            #pragma unroll
            for (int mi = 0; mi < 4; mi++)
                #pragma unroll
                for (int ni = 0; ni < 4; ni++)
                    asm volatile(
                        "mma.sync.aligned.m16n8k16.row.col.f32.bf16.bf16.f32 "
                        "{%0,%1,%2,%3}, {%4,%5,%6,%7}, {%8,%9}, {%0,%1,%2,%3};"
                        : "+f"(acc[mi][ni][0]), "+f"(acc[mi][ni][1]),
                          "+f"(acc[mi][ni][2]), "+f"(acc[mi][ni][3])
                        : "r"(afr[mi][0]), "r"(afr[mi][1]), "r"(afr[mi][2]), "r"(afr[mi][3]),
                          "r"(bfr[ni][0]), "r"(bfr[ni][1]));
        }
        __syncthreads();
        if (it + 2 < TOT) ISSUE(it + 2);
    }
    #undef ISSUE
    #undef AP
    #undef BP

    // epilogue
    #pragma unroll
    for (int mi = 0; mi < 4; mi++) {
        #pragma unroll
        for (int ni = 0; ni < 4; ni++) {
            int r0 = m0 + wm * 64 + mi * 16 + (lane >> 2);
            int c0 = n0 + wn * 32 + ni * 8 + (lane & 3) * 2;
            float v00 = acc[mi][ni][0], v01 = acc[mi][ni][1];
            float v10 = acc[mi][ni][2], v11 = acc[mi][ni][3];
            if (HASB) {
                float b0 = __ldg(&bias[c0]), b1 = __ldg(&bias[c0 + 1]);
                v00 += b0; v01 += b1; v10 += b0; v11 += b1;
            }
            if (EPI == 1) {
                v00 = fmaxf(v00, 0.f); v01 = fmaxf(v01, 0.f);
                v10 = fmaxf(v10, 0.f); v11 = fmaxf(v11, 0.f);
                uint32_t hp, lp;
                if (r0 < NN) {
                    size_t o = ((size_t)b * NN + r0) * DE + c0;
                    split_pack(v00, v01, hp, lp);
                    *(uint32_t*)&g_hh[o] = hp; *(uint32_t*)&g_hl[o] = lp;
                }
                if (r0 + 8 < NN) {
                    size_t o = ((size_t)b * NN + r0 + 8) * DE + c0;
                    split_pack(v10, v11, hp, lp);
                    *(uint32_t*)&g_hh[o] = hp; *(uint32_t*)&g_hl[o] = lp;
                }
            } else {
                float* O = (OSEL == 1) ? g_u : g_v;
                if (r0 < NN)
                    *(float2*)&O[((size_t)b * NN + r0) * DE + c0] = make_float2(v00, v01);
                if (r0 + 8 < NN)
                    *(float2*)&O[((size_t)b * NN + r0 + 8) * DE + c0] = make_float2(v10, v11);
            }
        }
    }
}

// ---------------- fused SAGE combine: g = relu(mean_e(U) + V) -----------------
template <bool FINAL>
__global__ void k_agg2() {
    int w = (blockIdx.x * blockDim.x + threadIdx.x) >> 5;
    int lane = threadIdx.x & 31;
    if (w >= BAGS * NN) return;
    int b = w / NN, i = w - b * NN;
    int r0 = g_rowptr[b * (NN + 1) + i];
    int r1 = g_rowptr[b * (NN + 1) + i + 1];
    const float* Ub = g_u + (size_t)b * NN * DE;
    const int* colb = g_col + b * EE;
    float a[8] = {0.f, 0.f, 0.f, 0.f, 0.f, 0.f, 0.f, 0.f};
    for (int e = r0; e < r1; e++) {
        int s = __ldg(&colb[e]);
        const float4* row = (const float4*)(Ub + (size_t)s * DE);
        float4 u0 = __ldg(&row[lane * 2]);
        float4 u1 = __ldg(&row[lane * 2 + 1]);
        a[0] += u0.x; a[1] += u0.y; a[2] += u0.z; a[3] += u0.w;
        a[4] += u1.x; a[5] += u1.y; a[6] += u1.z; a[7] += u1.w;
    }
    int dg = r1 - r0;
    float inv = 1.f / (float)(dg > 1 ? dg : 1);
    size_t base = ((size_t)b * NN + i) * DE + lane * 8;
    float4 v0 = *(const float4*)(g_v + base);
    float4 v1 = *(const float4*)(g_v + base + 4);
    float g[8];
    g[0] = fmaxf(a[0] * inv + v0.x, 0.f); g[1] = fmaxf(a[1] * inv + v0.y, 0.f);
    g[2] = fmaxf(a[2] * inv + v0.z, 0.f); g[3] = fmaxf(a[3] * inv + v0.w, 0.f);
    g[4] = fmaxf(a[4] * inv + v1.x, 0.f); g[5] = fmaxf(a[5] * inv + v1.y, 0.f);
    g[6] = fmaxf(a[6] * inv + v1.z, 0.f); g[7] = fmaxf(a[7] * inv + v1.w, 0.f);
    if (!FINAL) {
        uint32_t hp[4], lp[4];
        #pragma unroll
        for (int q = 0; q < 4; q++) split_pack(g[2 * q], g[2 * q + 1], hp[q], lp[q]);
        *(uint4*)(&g_hh[base]) = *(uint4*)hp;
        *(uint4*)(&g_hl[base]) = *(uint4*)lp;
    } else {
        *(float4*)(&g_g2[base])     = make_float4(g[0], g[1], g[2], g[3]);
        *(float4*)(&g_g2[base + 4]) = make_float4(g[4], g[5], g[6], g[7]);
    }
}

// ---------------- pooled embedding + classifier -------------------------------
__global__ void k_reduce() {
    int b = blockIdx.y, c = threadIdx.x;
    int i0 = blockIdx.x * 250, i1 = i0 + 250;
    const float* Gb = g_g2 + (size_t)b * NN * DE;
    float s = 0.f;
    for (int i = i0; i < i1; i++) s += Gb[(size_t)i * DE + c];
    atomicAdd(&g_emb[b * DE + c], s);
}
__global__ void k_cls(const float* __restrict__ Wc1, const float* __restrict__ bc1,
                      const float* __restrict__ Wc2, const float* __restrict__ bc2,
                      float* __restrict__ out) {
    int b = blockIdx.x, t = threadIdx.x;   // 128 threads
    __shared__ float es[256];
    __shared__ float r0[128], r1[128];
    es[t]       = g_emb[b * DE + t];
    es[t + 128] = g_emb[b * DE + t + 128];
    __syncthreads();
    float a = bc1[t];
    #pragma unroll 8
    for (int k = 0; k < 256; k++) a += es[k] * Wc1[k * 128 + t];
    float h1 = fmaxf(a, 0.f);
    r0[t] = h1 * Wc2[t * 2 + 0];
    r1[t] = h1 * Wc2[t * 2 + 1];
    __syncthreads();
    for (int off = 64; off > 0; off >>= 1) {
        if (t < off) { r0[t] += r0[t + off]; r1[t] += r1[t + off]; }
        __syncthreads();
    }
    if (t == 0) {
        out[b * 2 + 0] = r0[0] + bc2[0];
        out[b * 2 + 1] = r1[0] + bc2[1];
    }
}

// ---------------- launch ------------------------------------------------------
extern "C" void kernel_launch(void* const* d_in, const int* in_sizes, int n_in,
                              void* d_out, int out_size) {
    (void)in_sizes; (void)n_in; (void)out_size;
    const float* x   = (const float*)d_in[0];
    const int*   ei  = (const int*)d_in[1];       // int32 (JAX x64 disabled)
    const float* We  = (const float*)d_in[2];
    const float* be  = (const float*)d_in[3];
    const float* Wl1 = (const float*)d_in[4];
    const float* bl1 = (const float*)d_in[5];
    const float* Wr1 = (const float*)d_in[6];
    const float* Wl2 = (const float*)d_in[7];
    const float* bl2 = (const float*)d_in[8];
    const float* Wr2 = (const float*)d_in[9];
    // d_in[10..12] (Wlp, blp, Wrp) dead: softmax over a size-1 axis == 1
    const float* Wc1 = (const float*)d_in[13];
    const float* bc1 = (const float*)d_in[14];
    const float* Wc2 = (const float*)d_in[15];
    const float* bc2 = (const float*)d_in[16];
    float* out = (float*)d_out;

    dim3 mma_grid((NN + 127) / 128, 2, BAGS);    // (40, 2, 16)
    dim3 edge_grid((EE + 255) / 256, BAGS);

    k_zero<<<(BAGS * NN + 255) / 256, 256>>>();
    k_cvtx<<<(BAGS * NN * DIN + 255) / 256, 256>>>(x);
    k_cvtw<0, 128><<<(256 * 128 + 255) / 256, 256>>>(We);
    k_cvtw<1, 256><<<(256 * 256 + 255) / 256, 256>>>(Wl1);
    k_cvtw<2, 256><<<(256 * 256 + 255) / 256, 256>>>(Wr1);
    k_cvtw<3, 256><<<(256 * 256 + 255) / 256, 256>>>(Wl2);
    k_cvtw<4, 256><<<(256 * 256 + 255) / 256, 256>>>(Wr2);
    // CSR
    k_deg<<<edge_grid, 256>>>(ei);
    k_scan<<<BAGS, 1024>>>();
    k_fill<<<edge_grid, 256>>>(ei);
    // encoder: h = relu(x@We + be) -> bf16 pair
    k_mma<128, 0, 0, 0, 1, true><<<mma_grid, 256>>>(be);
    // layer 1: u = h@Wl1 ; v = h@Wr1 + bl1 ; g1 = relu(mean(u)+v) -> pair
    k_mma<256, 1, 1, 1, 0, false><<<mma_grid, 256>>>(nullptr);
    k_mma<256, 1, 2, 2, 0, true><<<mma_grid, 256>>>(bl1);
    k_agg2<false><<<(BAGS * NN) / 8, 256>>>();
    // layer 2
    k_mma<256, 1, 3, 1, 0, false><<<mma_grid, 256>>>(nullptr);
    k_mma<256, 1, 4, 2, 0, true><<<mma_grid, 256>>>(bl2);
    k_agg2<true><<<(BAGS * NN) / 8, 256>>>();
    // pool + classify
    k_reduce<<<dim3(20, BAGS), 256>>>();
    k_cls<<<BAGS, 128>>>(Wc1, bc1, Wc2, bc2, out);
}

// round 7
// speedup vs baseline: 1.5942x; 1.1697x over previous
#include <cuda_runtime.h>
#include <cuda_bf16.h>
#include <cstdint>

#define BAGS 16
#define NN   5000
#define EE   160000
#define DE   256
#define DIN  128

// ---------------- scratch (device globals) -----------------------------------
__device__ __align__(16) __nv_bfloat16 g_xh[BAGS*NN*DIN], g_xl[BAGS*NN*DIN];
__device__ __align__(16) __nv_bfloat16 g_hh[BAGS*NN*DE],  g_hl[BAGS*NN*DE];   // h, later g1
__device__ __align__(16) __nv_bfloat16 g_ub[BAGS*NN*DE];  // u in bf16 (gathered)
__device__ __align__(16) float g_v [BAGS*NN*DE];
__device__ __align__(16) float g_g2[BAGS*NN*DE];
__device__ float g_emb[BAGS*DE];
// transposed split weights:  Wt[n][k] = W[k][n]
__device__ __align__(16) __nv_bfloat16 g_weth[DE*DIN], g_wetl[DE*DIN];
__device__ __align__(16) __nv_bfloat16 g_w1h[DE*DE], g_w1l[DE*DE];   // Wl1^T
__device__ __align__(16) __nv_bfloat16 g_w2h[DE*DE], g_w2l[DE*DE];   // Wr1^T
__device__ __align__(16) __nv_bfloat16 g_w3h[DE*DE], g_w3l[DE*DE];   // Wl2^T
__device__ __align__(16) __nv_bfloat16 g_w4h[DE*DE], g_w4l[DE*DE];   // Wr2^T
// CSR
__device__ int g_deg[BAGS*NN], g_rowptr[BAGS*(NN+1)], g_cursor[BAGS*NN], g_col[BAGS*EE];

// ---------------- helpers -----------------------------------------------------
__device__ __forceinline__ uint32_t smem_u32(const void* p) {
    uint32_t a;
    asm("{ .reg .u64 t; cvta.to.shared.u64 t, %1; cvt.u32.u64 %0, t; }" : "=r"(a) : "l"(p));
    return a;
}
__device__ __forceinline__ void split_pack(float v0, float v1, uint32_t& hp, uint32_t& lp) {
    __nv_bfloat16 h0 = __float2bfloat16(v0), h1 = __float2bfloat16(v1);
    __nv_bfloat16 l0 = __float2bfloat16(v0 - __bfloat162float(h0));
    __nv_bfloat16 l1 = __float2bfloat16(v1 - __bfloat162float(h1));
    hp = (uint32_t)__bfloat16_as_ushort(h0) | ((uint32_t)__bfloat16_as_ushort(h1) << 16);
    lp = (uint32_t)__bfloat16_as_ushort(l0) | ((uint32_t)__bfloat16_as_ushort(l1) << 16);
}
__device__ __forceinline__ uint32_t pack_bf16(float v0, float v1) {
    return (uint32_t)__bfloat16_as_ushort(__float2bfloat16(v0)) |
           ((uint32_t)__bfloat16_as_ushort(__float2bfloat16(v1)) << 16);
}
__device__ __forceinline__ float2 bf2f(uint32_t w) {
    __nv_bfloat162 h = *reinterpret_cast<__nv_bfloat162*>(&w);
    return __bfloat1622float2(h);
}

// selectors
template <int S> __device__ __forceinline__ const __nv_bfloat16* apair(int lo) {
    if (S == 0) return lo ? g_xl : g_xh;
    return lo ? g_hl : g_hh;
}
template <int S> __device__ __forceinline__ __nv_bfloat16* wpair(int lo) {
    switch (S) {
        case 0:  return lo ? g_wetl : g_weth;
        case 1:  return lo ? g_w1l : g_w1h;
        case 2:  return lo ? g_w2l : g_w2h;
        case 3:  return lo ? g_w3l : g_w3h;
        default: return lo ? g_w4l : g_w4h;
    }
}

// ---------------- prep kernels ------------------------------------------------
__global__ void k_zero() {
    int i = blockIdx.x * blockDim.x + threadIdx.x;
    if (i < BAGS * NN) g_deg[i] = 0;
    if (i < BAGS * DE) g_emb[i] = 0.f;
}
__global__ void k_cvtx(const float* __restrict__ x) {
    int i = blockIdx.x * blockDim.x + threadIdx.x;
    if (i >= BAGS * NN * DIN) return;
    float v = x[i];
    __nv_bfloat16 h = __float2bfloat16(v);
    g_xh[i] = h;
    g_xl[i] = __float2bfloat16(v - __bfloat162float(h));
}
template <int WSEL, int K>
__global__ void k_cvtw(const float* __restrict__ W) {
    int i = blockIdx.x * blockDim.x + threadIdx.x;
    if (i >= 256 * K) return;
    int n = i / K, k = i - n * K;
    float v = W[k * 256 + n];
    __nv_bfloat16 h = __float2bfloat16(v);
    wpair<WSEL>(0)[i] = h;
    wpair<WSEL>(1)[i] = __float2bfloat16(v - __bfloat162float(h));
}

// ---------------- CSR build ---------------------------------------------------
__global__ void k_deg(const int* __restrict__ ei) {
    int e = blockIdx.x * blockDim.x + threadIdx.x;
    int b = blockIdx.y;
    if (e >= EE) return;
    int dst = ei[(size_t)b * 2 * EE + EE + e];
    if ((unsigned)dst >= NN) return;
    atomicAdd(&g_deg[b * NN + dst], 1);
}
__global__ void k_scan() {
    int b = blockIdx.x, t = threadIdx.x;
    __shared__ int sh[1024];
    int carry = 0;
    for (int c = 0; c < 5; c++) {
        int idx = c * 1024 + t;
        int v = (idx < NN) ? g_deg[b * NN + idx] : 0;
        sh[t] = v;
        __syncthreads();
        for (int off = 1; off < 1024; off <<= 1) {
            int add = (t >= off) ? sh[t - off] : 0;
            __syncthreads();
            sh[t] += add;
            __syncthreads();
        }
        int excl = sh[t] - v;
        if (idx < NN) {
            g_rowptr[b * (NN + 1) + idx] = carry + excl;
            g_cursor[b * NN + idx] = carry + excl;
        }
        int tot = sh[1023];
        __syncthreads();
        carry += tot;
    }
    if (t == 0) g_rowptr[b * (NN + 1) + NN] = carry;
}
__global__ void k_fill(const int* __restrict__ ei) {
    int e = blockIdx.x * blockDim.x + threadIdx.x;
    int b = blockIdx.y;
    if (e >= EE) return;
    int src = ei[(size_t)b * 2 * EE + e];
    int dst = ei[(size_t)b * 2 * EE + EE + e];
    if ((unsigned)dst >= NN || (unsigned)src >= NN) return;
    int p = atomicAdd(&g_cursor[b * NN + dst], 1);
    g_col[b * EE + p] = src;
}

// ---------------- HMMA GEMM  C[m,n] = sum_k A[m,k] * Wt[n,k] ------------------
// BM=128, BN=128, BK=32, 256 threads (8 warps, 2x4), warp tile 64x32.
// 3 precision passes: AhBh, AhBl, AlBh accumulated in fp32. ldmatrix fragments.
#define PITCH 80

__device__ __forceinline__ void issue_chunk(
    const __nv_bfloat16* __restrict__ Agl, const __nv_bfloat16* __restrict__ Bgl,
    int KD, int m0, int kc, char* sA, char* sB, int tid)
{
    #pragma unroll
    for (int v = 0; v < 2; v++) {
        int idx = v * 256 + tid;
        int row = idx >> 2, c16 = idx & 3;
        int gr = m0 + row;
        const void* src = Agl + (size_t)gr * KD + kc + c16 * 8;
        uint32_t dst = smem_u32(sA + row * PITCH + c16 * 16);
        int sz = (gr < NN) ? 16 : 0;
        asm volatile("cp.async.cg.shared.global [%0], [%1], 16, %2;"
                     :: "r"(dst), "l"(src), "r"(sz));
    }
    #pragma unroll
    for (int v = 0; v < 2; v++) {
        int idx = v * 256 + tid;
        int row = idx >> 2, c16 = idx & 3;
        const void* src = Bgl + (size_t)row * KD + kc + c16 * 8;
        uint32_t dst = smem_u32(sB + row * PITCH + c16 * 16);
        asm volatile("cp.async.cg.shared.global [%0], [%1], 16;"
                     :: "r"(dst), "l"(src));
    }
    asm volatile("cp.async.commit_group;");
}

// EPI 0: (+bias if HASB) -> bf16 into g_ub (OSEL=1) or fp32 into g_v (OSEL=2)
// EPI 1: relu(acc+bias) -> split bf16 pair into g_hh/g_hl
template <int KD, int ASEL, int WSEL, int OSEL, int EPI, bool HASB>
__global__ void __launch_bounds__(256, 1) k_mma(const float* __restrict__ bias) {
    __shared__ __align__(16) char smA[2][128 * PITCH];
    __shared__ __align__(16) char smB[2][128 * PITCH];

    int tid = threadIdx.x, lane = tid & 31, warp = tid >> 5;
    int wm = warp & 1, wn = warp >> 1;               // 2 x 4 warp grid
    int m0 = blockIdx.x * 128, n0 = blockIdx.y * 128, b = blockIdx.z;

    const __nv_bfloat16* Ah = apair<ASEL>(0) + (size_t)b * NN * KD;
    const __nv_bfloat16* Al = apair<ASEL>(1) + (size_t)b * NN * KD;
    const __nv_bfloat16* Bh = wpair<WSEL>(0) + (size_t)n0 * KD;
    const __nv_bfloat16* Bl = wpair<WSEL>(1) + (size_t)n0 * KD;

    const int NCH = KD / 32, TOT = 3 * NCH;
    float acc[4][4][4] = {};

    #define AP(p) ((p) == 2 ? Al : Ah)
    #define BP(p) ((p) == 1 ? Bl : Bh)
    #define ISSUE(it) do { int _p = (it) / NCH, _c = (it) % NCH;                     \
        issue_chunk(AP(_p), BP(_p), KD, m0, _c * 32,                                 \
                    smA[(it) & 1], smB[(it) & 1], tid); } while (0)

    ISSUE(0);
    ISSUE(1);

    for (int it = 0; it < TOT; it++) {
        if (it + 1 < TOT) asm volatile("cp.async.wait_group 1;");
        else              asm volatile("cp.async.wait_group 0;");
        __syncthreads();

        const char* sA = smA[it & 1];
        const char* sB = smB[it & 1];
        #pragma unroll
        for (int ks = 0; ks < 2; ks++) {
            uint32_t afr[4][4];
            #pragma unroll
            for (int mi = 0; mi < 4; mi++) {
                uint32_t ad = smem_u32(sA + (wm * 64 + mi * 16 + (lane & 15)) * PITCH
                                          + ks * 32 + (lane >> 4) * 16);
                asm volatile("ldmatrix.sync.aligned.m8n8.x4.shared.b16 {%0,%1,%2,%3}, [%4];"
                             : "=r"(afr[mi][0]), "=r"(afr[mi][1]),
                               "=r"(afr[mi][2]), "=r"(afr[mi][3]) : "r"(ad));
            }
            uint32_t bfr[4][2];
            #pragma unroll
            for (int q = 0; q < 2; q++) {
                int g = lane >> 3;          // 0..3 address group
                uint32_t bd = smem_u32(sB + (wn * 32 + q * 16 + (g >> 1) * 8 + (lane & 7)) * PITCH
                                          + ks * 32 + (g & 1) * 16);
                asm volatile("ldmatrix.sync.aligned.m8n8.x4.shared.b16 {%0,%1,%2,%3}, [%4];"
                             : "=r"(bfr[2 * q][0]), "=r"(bfr[2 * q][1]),
                               "=r"(bfr[2 * q + 1][0]), "=r"(bfr[2 * q + 1][1]) : "r"(bd));
            }
            #pragma unroll
            for (int mi = 0; mi < 4; mi++)
                #pragma unroll
                for (int ni = 0; ni < 4; ni++)
                    asm volatile(
                        "mma.sync.aligned.m16n8k16.row.col.f32.bf16.bf16.f32 "
                        "{%0,%1,%2,%3}, {%4,%5,%6,%7}, {%8,%9}, {%0,%1,%2,%3};"
                        : "+f"(acc[mi][ni][0]), "+f"(acc[mi][ni][1]),
                          "+f"(acc[mi][ni][2]), "+f"(acc[mi][ni][3])
                        : "r"(afr[mi][0]), "r"(afr[mi][1]), "r"(afr[mi][2]), "r"(afr[mi][3]),
                          "r"(bfr[ni][0]), "r"(bfr[ni][1]));
        }
        __syncthreads();
        if (it + 2 < TOT) ISSUE(it + 2);
    }
    #undef ISSUE
    #undef AP
    #undef BP

    // epilogue
    #pragma unroll
    for (int mi = 0; mi < 4; mi++) {
        #pragma unroll
        for (int ni = 0; ni < 4; ni++) {
            int r0 = m0 + wm * 64 + mi * 16 + (lane >> 2);
            int c0 = n0 + wn * 32 + ni * 8 + (lane & 3) * 2;
            float v00 = acc[mi][ni][0], v01 = acc[mi][ni][1];
            float v10 = acc[mi][ni][2], v11 = acc[mi][ni][3];
            if (HASB) {
                float b0 = __ldg(&bias[c0]), b1 = __ldg(&bias[c0 + 1]);
                v00 += b0; v01 += b1; v10 += b0; v11 += b1;
            }
            if (EPI == 1) {
                v00 = fmaxf(v00, 0.f); v01 = fmaxf(v01, 0.f);
                v10 = fmaxf(v10, 0.f); v11 = fmaxf(v11, 0.f);
                uint32_t hp, lp;
                if (r0 < NN) {
                    size_t o = ((size_t)b * NN + r0) * DE + c0;
                    split_pack(v00, v01, hp, lp);
                    *(uint32_t*)&g_hh[o] = hp; *(uint32_t*)&g_hl[o] = lp;
                }
                if (r0 + 8 < NN) {
                    size_t o = ((size_t)b * NN + r0 + 8) * DE + c0;
                    split_pack(v10, v11, hp, lp);
                    *(uint32_t*)&g_hh[o] = hp; *(uint32_t*)&g_hl[o] = lp;
                }
            } else if (OSEL == 1) {            // u -> bf16
                if (r0 < NN)
                    *(uint32_t*)&g_ub[((size_t)b * NN + r0) * DE + c0] = pack_bf16(v00, v01);
                if (r0 + 8 < NN)
                    *(uint32_t*)&g_ub[((size_t)b * NN + r0 + 8) * DE + c0] = pack_bf16(v10, v11);
            } else {                           // v -> fp32
                if (r0 < NN)
                    *(float2*)&g_v[((size_t)b * NN + r0) * DE + c0] = make_float2(v00, v01);
                if (r0 + 8 < NN)
                    *(float2*)&g_v[((size_t)b * NN + r0 + 8) * DE + c0] = make_float2(v10, v11);
            }
        }
    }
}

// ---------------- fused SAGE combine: g = relu(mean_e(U) + V) -----------------
// U rows are bf16 (512B) -> one LDG.128 per lane per edge.
template <bool FINAL>
__global__ void k_agg2() {
    int w = (blockIdx.x * blockDim.x + threadIdx.x) >> 5;
    int lane = threadIdx.x & 31;
    if (w >= BAGS * NN) return;
    int b = w / NN, i = w - b * NN;
    int r0 = g_rowptr[b * (NN + 1) + i];
    int r1 = g_rowptr[b * (NN + 1) + i + 1];
    const __nv_bfloat16* Ub = g_ub + (size_t)b * NN * DE;
    const int* colb = g_col + b * EE;
    float a[8] = {0.f, 0.f, 0.f, 0.f, 0.f, 0.f, 0.f, 0.f};
    for (int e = r0; e < r1; e++) {
        int s = __ldg(&colb[e]);
        uint4 r = __ldg((const uint4*)(Ub + (size_t)s * DE) + lane);
        float2 p0 = bf2f(r.x), p1 = bf2f(r.y), p2 = bf2f(r.z), p3 = bf2f(r.w);
        a[0] += p0.x; a[1] += p0.y; a[2] += p1.x; a[3] += p1.y;
        a[4] += p2.x; a[5] += p2.y; a[6] += p3.x; a[7] += p3.y;
    }
    int dg = r1 - r0;
    float inv = 1.f / (float)(dg > 1 ? dg : 1);
    size_t base = ((size_t)b * NN + i) * DE + lane * 8;
    float4 v0 = *(const float4*)(g_v + base);
    float4 v1 = *(const float4*)(g_v + base + 4);
    float g[8];
    g[0] = fmaxf(a[0] * inv + v0.x, 0.f); g[1] = fmaxf(a[1] * inv + v0.y, 0.f);
    g[2] = fmaxf(a[2] * inv + v0.z, 0.f); g[3] = fmaxf(a[3] * inv + v0.w, 0.f);
    g[4] = fmaxf(a[4] * inv + v1.x, 0.f); g[5] = fmaxf(a[5] * inv + v1.y, 0.f);
    g[6] = fmaxf(a[6] * inv + v1.z, 0.f); g[7] = fmaxf(a[7] * inv + v1.w, 0.f);
    if (!FINAL) {
        uint32_t hp[4], lp[4];
        #pragma unroll
        for (int q = 0; q < 4; q++) split_pack(g[2 * q], g[2 * q + 1], hp[q], lp[q]);
        *(uint4*)(&g_hh[base]) = *(uint4*)hp;
        *(uint4*)(&g_hl[base]) = *(uint4*)lp;
    } else {
        *(float4*)(&g_g2[base])     = make_float4(g[0], g[1], g[2], g[3]);
        *(float4*)(&g_g2[base + 4]) = make_float4(g[4], g[5], g[6], g[7]);
    }
}

// ---------------- pooled embedding + classifier -------------------------------
__global__ void k_reduce() {
    int b = blockIdx.y, c = threadIdx.x;
    int i0 = blockIdx.x * 250, i1 = i0 + 250;
    const float* Gb = g_g2 + (size_t)b * NN * DE;
    float s = 0.f;
    for (int i = i0; i < i1; i++) s += Gb[(size_t)i * DE + c];
    atomicAdd(&g_emb[b * DE + c], s);
}
__global__ void k_cls(const float* __restrict__ Wc1, const float* __restrict__ bc1,
                      const float* __restrict__ Wc2, const float* __restrict__ bc2,
                      float* __restrict__ out) {
    int b = blockIdx.x, t = threadIdx.x;   // 128 threads
    __shared__ float es[256];
    __shared__ float r0[128], r1[128];
    es[t]       = g_emb[b * DE + t];
    es[t + 128] = g_emb[b * DE + t + 128];
    __syncthreads();
    float a = bc1[t];
    #pragma unroll 8
    for (int k = 0; k < 256; k++) a += es[k] * Wc1[k * 128 + t];
    float h1 = fmaxf(a, 0.f);
    r0[t] = h1 * Wc2[t * 2 + 0];
    r1[t] = h1 * Wc2[t * 2 + 1];
    __syncthreads();
    for (int off = 64; off > 0; off >>= 1) {
        if (t < off) { r0[t] += r0[t + off]; r1[t] += r1[t + off]; }
        __syncthreads();
    }
    if (t == 0) {
        out[b * 2 + 0] = r0[0] + bc2[0];
        out[b * 2 + 1] = r1[0] + bc2[1];
    }
}

// ---------------- launch ------------------------------------------------------
extern "C" void kernel_launch(void* const* d_in, const int* in_sizes, int n_in,
                              void* d_out, int out_size) {
    (void)in_sizes; (void)n_in; (void)out_size;
    const float* x   = (const float*)d_in[0];
    const int*   ei  = (const int*)d_in[1];       // int32 (JAX x64 disabled)
    const float* We  = (const float*)d_in[2];
    const float* be  = (const float*)d_in[3];
    const float* Wl1 = (const float*)d_in[4];
    const float* bl1 = (const float*)d_in[5];
    const float* Wr1 = (const float*)d_in[6];
    const float* Wl2 = (const float*)d_in[7];
    const float* bl2 = (const float*)d_in[8];
    const float* Wr2 = (const float*)d_in[9];
    // d_in[10..12] (Wlp, blp, Wrp) dead: softmax over a size-1 axis == 1
    const float* Wc1 = (const float*)d_in[13];
    const float* bc1 = (const float*)d_in[14];
    const float* Wc2 = (const float*)d_in[15];
    const float* bc2 = (const float*)d_in[16];
    float* out = (float*)d_out;

    dim3 mma_grid((NN + 127) / 128, 2, BAGS);    // (40, 2, 16)
    dim3 edge_grid((EE + 255) / 256, BAGS);

    k_zero<<<(BAGS * NN + 255) / 256, 256>>>();
    k_cvtx<<<(BAGS * NN * DIN + 255) / 256, 256>>>(x);
    k_cvtw<0, 128><<<(256 * 128 + 255) / 256, 256>>>(We);
    k_cvtw<1, 256><<<(256 * 256 + 255) / 256, 256>>>(Wl1);
    k_cvtw<2, 256><<<(256 * 256 + 255) / 256, 256>>>(Wr1);
    k_cvtw<3, 256><<<(256 * 256 + 255) / 256, 256>>>(Wl2);
    k_cvtw<4, 256><<<(256 * 256 + 255) / 256, 256>>>(Wr2);
    // CSR
    k_deg<<<edge_grid, 256>>>(ei);
    k_scan<<<BAGS, 1024>>>();
    k_fill<<<edge_grid, 256>>>(ei);
    // encoder: h = relu(x@We + be) -> bf16 pair
    k_mma<128, 0, 0, 0, 1, true><<<mma_grid, 256>>>(be);
    // layer 1: u = h@Wl1 (bf16) ; v = h@Wr1 + bl1 ; g1 = relu(mean(u)+v) -> pair
    k_mma<256, 1, 1, 1, 0, false><<<mma_grid, 256>>>(nullptr);
    k_mma<256, 1, 2, 2, 0, true><<<mma_grid, 256>>>(bl1);
    k_agg2<false><<<(BAGS * NN) / 8, 256>>>();
    // layer 2
    k_mma<256, 1, 3, 1, 0, false><<<mma_grid, 256>>>(nullptr);
    k_mma<256, 1, 4, 2, 0, true><<<mma_grid, 256>>>(bl2);
    k_agg2<true><<<(BAGS * NN) / 8, 256>>>();
    // pool + classify
    k_reduce<<<dim3(20, BAGS), 256>>>();
    k_cls<<<BAGS, 128>>>(Wc1, bc1, Wc2, bc2, out);
}

// round 9
// speedup vs baseline: 1.7392x; 1.0909x over previous
#include <cuda_runtime.h>
#include <cuda_bf16.h>
#include <cstdint>

#define BAGS 16
#define NN   5000
#define EE   160000
#define DE   256
#define DIN  128

// ---------------- scratch (device globals) -----------------------------------
__device__ __align__(16) __nv_bfloat16 g_xh[BAGS*NN*DIN], g_xl[BAGS*NN*DIN];
__device__ __align__(16) __nv_bfloat16 g_hh[BAGS*NN*DE],  g_hl[BAGS*NN*DE];   // h, later g1
__device__ __align__(16) __nv_bfloat16 g_ub[BAGS*NN*DE];  // u in bf16 (gathered)
__device__ __align__(16) float g_v [BAGS*NN*DE];
__device__ __align__(16) float g_g2[BAGS*NN*DE];
__device__ float g_emb[BAGS*DE];
// transposed split weights:  Wt[n][k] = W[k][n]
__device__ __align__(16) __nv_bfloat16 g_weth[DE*DIN], g_wetl[DE*DIN];
__device__ __align__(16) __nv_bfloat16 g_w1h[DE*DE], g_w1l[DE*DE];   // Wl1^T
__device__ __align__(16) __nv_bfloat16 g_w2h[DE*DE], g_w2l[DE*DE];   // Wr1^T
__device__ __align__(16) __nv_bfloat16 g_w3h[DE*DE], g_w3l[DE*DE];   // Wl2^T
__device__ __align__(16) __nv_bfloat16 g_w4h[DE*DE], g_w4l[DE*DE];   // Wr2^T
// CSR
__device__ int g_deg[BAGS*NN], g_rowptr[BAGS*(NN+1)], g_cursor[BAGS*NN], g_col[BAGS*EE];

// ---------------- helpers -----------------------------------------------------
__device__ __forceinline__ uint32_t smem_u32(const void* p) {
    uint32_t a;
    asm("{ .reg .u64 t; cvta.to.shared.u64 t, %1; cvt.u32.u64 %0, t; }" : "=r"(a) : "l"(p));
    return a;
}
__device__ __forceinline__ void split_pack(float v0, float v1, uint32_t& hp, uint32_t& lp) {
    __nv_bfloat16 h0 = __float2bfloat16(v0), h1 = __float2bfloat16(v1);
    __nv_bfloat16 l0 = __float2bfloat16(v0 - __bfloat162float(h0));
    __nv_bfloat16 l1 = __float2bfloat16(v1 - __bfloat162float(h1));
    hp = (uint32_t)__bfloat16_as_ushort(h0) | ((uint32_t)__bfloat16_as_ushort(h1) << 16);
    lp = (uint32_t)__bfloat16_as_ushort(l0) | ((uint32_t)__bfloat16_as_ushort(l1) << 16);
}
__device__ __forceinline__ uint32_t pack_bf16(float v0, float v1) {
    return (uint32_t)__bfloat16_as_ushort(__float2bfloat16(v0)) |
           ((uint32_t)__bfloat16_as_ushort(__float2bfloat16(v1)) << 16);
}
__device__ __forceinline__ float2 bf2f(uint32_t w) {
    __nv_bfloat162 h = *reinterpret_cast<__nv_bfloat162*>(&w);
    return __bfloat1622float2(h);
}

template <int S> __device__ __forceinline__ __nv_bfloat16* wpair(int lo) {
    switch (S) {
        case 0:  return lo ? g_wetl : g_weth;
        case 1:  return lo ? g_w1l : g_w1h;
        case 2:  return lo ? g_w2l : g_w2h;
        case 3:  return lo ? g_w3l : g_w3h;
        default: return lo ? g_w4l : g_w4h;
    }
}

// ---------------- prep kernels ------------------------------------------------
__global__ void k_zero() {
    int i = blockIdx.x * blockDim.x + threadIdx.x;
    if (i < BAGS * NN) g_deg[i] = 0;
    if (i < BAGS * DE) g_emb[i] = 0.f;
}
__global__ void k_cvtx(const float* __restrict__ x) {
    int i = blockIdx.x * blockDim.x + threadIdx.x;
    if (i >= BAGS * NN * DIN) return;
    float v = x[i];
    __nv_bfloat16 h = __float2bfloat16(v);
    g_xh[i] = h;
    g_xl[i] = __float2bfloat16(v - __bfloat162float(h));
}
__global__ void k_cvtwe(const float* __restrict__ W) {
    int i = blockIdx.x * blockDim.x + threadIdx.x;
    if (i >= 256 * 128) return;
    int n = i >> 7, k = i & 127;
    float v = W[k * 256 + n];
    __nv_bfloat16 h = __float2bfloat16(v);
    g_weth[i] = h;
    g_wetl[i] = __float2bfloat16(v - __bfloat162float(h));
}
__global__ void k_cvtw4(const float* __restrict__ W1, const float* __restrict__ W2,
                        const float* __restrict__ W3, const float* __restrict__ W4) {
    int i = blockIdx.x * blockDim.x + threadIdx.x;
    if (i >= 256 * 256) return;
    int w = blockIdx.y;
    const float* W = (w == 0) ? W1 : (w == 1) ? W2 : (w == 2) ? W3 : W4;
    __nv_bfloat16* Oh = (w == 0) ? g_w1h : (w == 1) ? g_w2h : (w == 2) ? g_w3h : g_w4h;
    __nv_bfloat16* Ol = (w == 0) ? g_w1l : (w == 1) ? g_w2l : (w == 2) ? g_w3l : g_w4l;
    int n = i >> 8, k = i & 255;
    float v = W[k * 256 + n];
    __nv_bfloat16 h = __float2bfloat16(v);
    Oh[i] = h;
    Ol[i] = __float2bfloat16(v - __bfloat162float(h));
}

// ---------------- CSR build ---------------------------------------------------
__global__ void k_deg(const int* __restrict__ ei) {
    int e = blockIdx.x * blockDim.x + threadIdx.x;
    int b = blockIdx.y;
    if (e >= EE) return;
    int dst = ei[(size_t)b * 2 * EE + EE + e];
    if ((unsigned)dst >= NN) return;
    atomicAdd(&g_deg[b * NN + dst], 1);
}
__global__ void k_scan() {
    int b = blockIdx.x, t = threadIdx.x;
    __shared__ int sh[1024];
    int carry = 0;
    for (int c = 0; c < 5; c++) {
        int idx = c * 1024 + t;
        int v = (idx < NN) ? g_deg[b * NN + idx] : 0;
        sh[t] = v;
        __syncthreads();
        for (int off = 1; off < 1024; off <<= 1) {
            int add = (t >= off) ? sh[t - off] : 0;
            __syncthreads();
            sh[t] += add;
            __syncthreads();
        }
        int excl = sh[t] - v;
        if (idx < NN) {
            g_rowptr[b * (NN + 1) + idx] = carry + excl;
            g_cursor[b * NN + idx] = carry + excl;
        }
        int tot = sh[1023];
        __syncthreads();
        carry += tot;
    }
    if (t == 0) g_rowptr[b * (NN + 1) + NN] = carry;
}
__global__ void k_fill(const int* __restrict__ ei) {
    int e = blockIdx.x * blockDim.x + threadIdx.x;
    int b = blockIdx.y;
    if (e >= EE) return;
    int src = ei[(size_t)b * 2 * EE + e];
    int dst = ei[(size_t)b * 2 * EE + EE + e];
    if ((unsigned)dst >= NN || (unsigned)src >= NN) return;
    int p = atomicAdd(&g_cursor[b * NN + dst], 1);
    g_col[b * EE + p] = src;
}

// ---------------- shared GEMM machinery ---------------------------------------
#define PITCH 80

__device__ __forceinline__ void issue_chunk(
    const __nv_bfloat16* __restrict__ Agl, const __nv_bfloat16* __restrict__ Bgl,
    int KD, int m0, int kc, char* sA, char* sB, int tid)
{
    #pragma unroll
    for (int v = 0; v < 2; v++) {
        int idx = v * 256 + tid;
        int row = idx >> 2, c16 = idx & 3;
        int gr = m0 + row;
        const void* src = Agl + (size_t)gr * KD + kc + c16 * 8;
        uint32_t dst = smem_u32(sA + row * PITCH + c16 * 16);
        int sz = (gr < NN) ? 16 : 0;
        asm volatile("cp.async.cg.shared.global [%0], [%1], 16, %2;"
                     :: "r"(dst), "l"(src), "r"(sz));
    }
    #pragma unroll
    for (int v = 0; v < 2; v++) {
        int idx = v * 256 + tid;
        int row = idx >> 2, c16 = idx & 3;
        const void* src = Bgl + (size_t)row * KD + kc + c16 * 8;
        uint32_t dst = smem_u32(sB + row * PITCH + c16 * 16);
        asm volatile("cp.async.cg.shared.global [%0], [%1], 16;"
                     :: "r"(dst), "l"(src));
    }
    asm volatile("cp.async.commit_group;");
}

__device__ __forceinline__ void mma_chunk(const char* sA, const char* sB,
                                          int wm, int wn, int lane, float acc[4][4][4]) {
    #pragma unroll
    for (int ks = 0; ks < 2; ks++) {
        uint32_t afr[4][4];
        #pragma unroll
        for (int mi = 0; mi < 4; mi++) {
            uint32_t ad = smem_u32(sA + (wm * 64 + mi * 16 + (lane & 15)) * PITCH
                                      + ks * 32 + (lane >> 4) * 16);
            asm volatile("ldmatrix.sync.aligned.m8n8.x4.shared.b16 {%0,%1,%2,%3}, [%4];"
                         : "=r"(afr[mi][0]), "=r"(afr[mi][1]),
                           "=r"(afr[mi][2]), "=r"(afr[mi][3]) : "r"(ad));
        }
        uint32_t bfr[4][2];
        #pragma unroll
        for (int q = 0; q < 2; q++) {
            int g = lane >> 3;
            uint32_t bd = smem_u32(sB + (wn * 32 + q * 16 + (g >> 1) * 8 + (lane & 7)) * PITCH
                                      + ks * 32 + (g & 1) * 16);
            asm volatile("ldmatrix.sync.aligned.m8n8.x4.shared.b16 {%0,%1,%2,%3}, [%4];"
                         : "=r"(bfr[2 * q][0]), "=r"(bfr[2 * q][1]),
                           "=r"(bfr[2 * q + 1][0]), "=r"(bfr[2 * q + 1][1]) : "r"(bd));
        }
        #pragma unroll
        for (int mi = 0; mi < 4; mi++)
            #pragma unroll
            for (int ni = 0; ni < 4; ni++)
                asm volatile(
                    "mma.sync.aligned.m16n8k16.row.col.f32.bf16.bf16.f32 "
                    "{%0,%1,%2,%3}, {%4,%5,%6,%7}, {%8,%9}, {%0,%1,%2,%3};"
                    : "+f"(acc[mi][ni][0]), "+f"(acc[mi][ni][1]),
                      "+f"(acc[mi][ni][2]), "+f"(acc[mi][ni][3])
                    : "r"(afr[mi][0]), "r"(afr[mi][1]), "r"(afr[mi][2]), "r"(afr[mi][3]),
                      "r"(bfr[ni][0]), "r"(bfr[ni][1]));
    }
}

// ---------------- encoder GEMM: h = relu(x@We + be) -> split pair -------------
__global__ void __launch_bounds__(256, 1) k_enc(const float* __restrict__ bias) {
    __shared__ __align__(16) char smA[2][128 * PITCH];
    __shared__ __align__(16) char smB[2][128 * PITCH];
    const int KD = DIN;
    int tid = threadIdx.x, lane = tid & 31, warp = tid >> 5;
    int wm = warp & 1, wn = warp >> 1;
    int m0 = blockIdx.x * 128, n0 = blockIdx.y * 128, b = blockIdx.z;

    const __nv_bfloat16* Ah = g_xh + (size_t)b * NN * KD;
    const __nv_bfloat16* Al = g_xl + (size_t)b * NN * KD;
    const __nv_bfloat16* Bh = g_weth + (size_t)n0 * KD;
    const __nv_bfloat16* Bl = g_wetl + (size_t)n0 * KD;

    const int NCH = KD / 32, TOT = 3 * NCH;
    float acc[4][4][4] = {};
    #define APE(it) (((it) / NCH) == 2 ? Al : Ah)
    #define BPE(it) (((it) / NCH) == 1 ? Bl : Bh)
    issue_chunk(APE(0), BPE(0), KD, m0, 0, smA[0], smB[0], tid);
    issue_chunk(APE(1), BPE(1), KD, m0, (1 % NCH) * 32, smA[1], smB[1], tid);
    for (int it = 0; it < TOT; it++) {
        if (it + 1 < TOT) asm volatile("cp.async.wait_group 1;");
        else              asm volatile("cp.async.wait_group 0;");
        __syncthreads();
        mma_chunk(smA[it & 1], smB[it & 1], wm, wn, lane, acc);
        __syncthreads();
        if (it + 2 < TOT)
            issue_chunk(APE(it + 2), BPE(it + 2), KD, m0, ((it + 2) % NCH) * 32,
                        smA[it & 1], smB[it & 1], tid);
    }
    #undef APE
    #undef BPE

    #pragma unroll
    for (int mi = 0; mi < 4; mi++)
        #pragma unroll
        for (int ni = 0; ni < 4; ni++) {
            int r0 = m0 + wm * 64 + mi * 16 + (lane >> 2);
            int c0 = n0 + wn * 32 + ni * 8 + (lane & 3) * 2;
            float b0 = __ldg(&bias[c0]), b1 = __ldg(&bias[c0 + 1]);
            float v00 = fmaxf(acc[mi][ni][0] + b0, 0.f), v01 = fmaxf(acc[mi][ni][1] + b1, 0.f);
            float v10 = fmaxf(acc[mi][ni][2] + b0, 0.f), v11 = fmaxf(acc[mi][ni][3] + b1, 0.f);
            uint32_t hp, lp;
            if (r0 < NN) {
                size_t o = ((size_t)b * NN + r0) * DE + c0;
                split_pack(v00, v01, hp, lp);
                *(uint32_t*)&g_hh[o] = hp; *(uint32_t*)&g_hl[o] = lp;
            }
            if (r0 + 8 < NN) {
                size_t o = ((size_t)b * NN + r0 + 8) * DE + c0;
                split_pack(v10, v11, hp, lp);
                *(uint32_t*)&g_hh[o] = hp; *(uint32_t*)&g_hl[o] = lp;
            }
        }
}

// ---------------- merged layer GEMM kernel ------------------------------------
// u (2 pass, keeps weight-lo correction): u = h@Wl -> bf16 g_ub   chunks [0,2N)
//   pass order: Ah*WLh, Ah*WLl  (Al*WLh dropped: node-decorrelated error only)
// v (3 pass): v = h@Wr + bias -> fp32 g_v                         chunks [2N,5N)
template <int WLSEL, int WRSEL>
__global__ void __launch_bounds__(256, 1) k_layer(const float* __restrict__ bias) {
    __shared__ __align__(16) char smA[2][128 * PITCH];
    __shared__ __align__(16) char smB[2][128 * PITCH];
    const int KD = DE;
    int tid = threadIdx.x, lane = tid & 31, warp = tid >> 5;
    int wm = warp & 1, wn = warp >> 1;
    int m0 = blockIdx.x * 128, n0 = blockIdx.y * 128, b = blockIdx.z;

    const __nv_bfloat16* Ah  = g_hh + (size_t)b * NN * KD;
    const __nv_bfloat16* Al  = g_hl + (size_t)b * NN * KD;
    const __nv_bfloat16* WLh = wpair<WLSEL>(0) + (size_t)n0 * KD;
    const __nv_bfloat16* WLl = wpair<WLSEL>(1) + (size_t)n0 * KD;
    const __nv_bfloat16* WRh = wpair<WRSEL>(0) + (size_t)n0 * KD;
    const __nv_bfloat16* WRl = wpair<WRSEL>(1) + (size_t)n0 * KD;

    const int NCH = KD / 32, TOT = 5 * NCH;
    float acc[4][4][4] = {};
    // chunk map: [0,N)=Ah*WLh [N,2N)=Ah*WLl | [2N,3N)=Ah*WRh [3N,4N)=Ah*WRl [4N,5N)=Al*WRh
    #define APL(it) ((it) >= 4 * NCH ? Al : Ah)
    #define BPL(it) ((it) < NCH ? WLh : ((it) < 2 * NCH ? WLl : \
                     ((it) < 3 * NCH ? WRh : ((it) < 4 * NCH ? WRl : WRh))))
    issue_chunk(APL(0), BPL(0), KD, m0, 0, smA[0], smB[0], tid);
    issue_chunk(APL(1), BPL(1), KD, m0, (1 % NCH) * 32, smA[1], smB[1], tid);
    for (int it = 0; it < TOT; it++) {
        if (it + 1 < TOT) asm volatile("cp.async.wait_group 1;");
        else              asm volatile("cp.async.wait_group 0;");
        __syncthreads();
        mma_chunk(smA[it & 1], smB[it & 1], wm, wn, lane, acc);
        __syncthreads();
        if (it + 2 < TOT)
            issue_chunk(APL(it + 2), BPL(it + 2), KD, m0, ((it + 2) % NCH) * 32,
                        smA[it & 1], smB[it & 1], tid);
        if (it == 2 * NCH - 1) {
            // u complete: write bf16, reset accumulators
            #pragma unroll
            for (int mi = 0; mi < 4; mi++)
                #pragma unroll
                for (int ni = 0; ni < 4; ni++) {
                    int r0 = m0 + wm * 64 + mi * 16 + (lane >> 2);
                    int c0 = n0 + wn * 32 + ni * 8 + (lane & 3) * 2;
                    if (r0 < NN)
                        *(uint32_t*)&g_ub[((size_t)b * NN + r0) * DE + c0] =
                            pack_bf16(acc[mi][ni][0], acc[mi][ni][1]);
                    if (r0 + 8 < NN)
                        *(uint32_t*)&g_ub[((size_t)b * NN + r0 + 8) * DE + c0] =
                            pack_bf16(acc[mi][ni][2], acc[mi][ni][3]);
                    acc[mi][ni][0] = acc[mi][ni][1] = acc[mi][ni][2] = acc[mi][ni][3] = 0.f;
                }
        }
    }
    #undef APL
    #undef BPL

    // v epilogue (+bias, fp32)
    #pragma unroll
    for (int mi = 0; mi < 4; mi++)
        #pragma unroll
        for (int ni = 0; ni < 4; ni++) {
            int r0 = m0 + wm * 64 + mi * 16 + (lane >> 2);
            int c0 = n0 + wn * 32 + ni * 8 + (lane & 3) * 2;
            float b0 = __ldg(&bias[c0]), b1 = __ldg(&bias[c0 + 1]);
            if (r0 < NN)
                *(float2*)&g_v[((size_t)b * NN + r0) * DE + c0] =
                    make_float2(acc[mi][ni][0] + b0, acc[mi][ni][1] + b1);
            if (r0 + 8 < NN)
                *(float2*)&g_v[((size_t)b * NN + r0 + 8) * DE + c0] =
                    make_float2(acc[mi][ni][2] + b0, acc[mi][ni][3] + b1);
        }
}

// ---------------- fused SAGE combine: g = relu(mean_e(U) + V) -----------------
template <bool FINAL>
__global__ void k_agg2() {
    int w = (blockIdx.x * blockDim.x + threadIdx.x) >> 5;
    int lane = threadIdx.x & 31;
    if (w >= BAGS * NN) return;
    int b = w / NN, i = w - b * NN;
    int r0 = g_rowptr[b * (NN + 1) + i];
    int r1 = g_rowptr[b * (NN + 1) + i + 1];
    const __nv_bfloat16* Ub = g_ub + (size_t)b * NN * DE;
    const int* colb = g_col + b * EE;
    float a[8] = {0.f, 0.f, 0.f, 0.f, 0.f, 0.f, 0.f, 0.f};
    for (int e = r0; e < r1; e++) {
        int s = __ldg(&colb[e]);
        uint4 r = __ldg((const uint4*)(Ub + (size_t)s * DE) + lane);
        float2 p0 = bf2f(r.x), p1 = bf2f(r.y), p2 = bf2f(r.z), p3 = bf2f(r.w);
        a[0] += p0.x; a[1] += p0.y; a[2] += p1.x; a[3] += p1.y;
        a[4] += p2.x; a[5] += p2.y; a[6] += p3.x; a[7] += p3.y;
    }
    int dg = r1 - r0;
    float inv = 1.f / (float)(dg > 1 ? dg : 1);
    size_t base = ((size_t)b * NN + i) * DE + lane * 8;
    float4 v0 = *(const float4*)(g_v + base);
    float4 v1 = *(const float4*)(g_v + base + 4);
    float g[8];
    g[0] = fmaxf(a[0] * inv + v0.x, 0.f); g[1] = fmaxf(a[1] * inv + v0.y, 0.f);
    g[2] = fmaxf(a[2] * inv + v0.z, 0.f); g[3] = fmaxf(a[3] * inv + v0.w, 0.f);
    g[4] = fmaxf(a[4] * inv + v1.x, 0.f); g[5] = fmaxf(a[5] * inv + v1.y, 0.f);
    g[6] = fmaxf(a[6] * inv + v1.z, 0.f); g[7] = fmaxf(a[7] * inv + v1.w, 0.f);
    if (!FINAL) {
        uint32_t hp[4], lp[4];
        #pragma unroll
        for (int q = 0; q < 4; q++) split_pack(g[2 * q], g[2 * q + 1], hp[q], lp[q]);
        *(uint4*)(&g_hh[base]) = *(uint4*)hp;
        *(uint4*)(&g_hl[base]) = *(uint4*)lp;
    } else {
        *(float4*)(&g_g2[base])     = make_float4(g[0], g[1], g[2], g[3]);
        *(float4*)(&g_g2[base + 4]) = make_float4(g[4], g[5], g[6], g[7]);
    }
}

// ---------------- pooled embedding + classifier -------------------------------
__global__ void k_reduce() {
    int b = blockIdx.y, c = threadIdx.x;
    int i0 = blockIdx.x * 250, i1 = i0 + 250;
    const float* Gb = g_g2 + (size_t)b * NN * DE;
    float s = 0.f;
    for (int i = i0; i < i1; i++) s += Gb[(size_t)i * DE + c];
    atomicAdd(&g_emb[b * DE + c], s);
}
__global__ void k_cls(const float* __restrict__ Wc1, const float* __restrict__ bc1,
                      const float* __restrict__ Wc2, const float* __restrict__ bc2,
                      float* __restrict__ out) {
    int b = blockIdx.x, t = threadIdx.x;   // 128 threads
    __shared__ float es[256];
    __shared__ float r0[128], r1[128];
    es[t]       = g_emb[b * DE + t];
    es[t + 128] = g_emb[b * DE + t + 128];
    __syncthreads();
    float a = bc1[t];
    #pragma unroll 8
    for (int k = 0; k < 256; k++) a += es[k] * Wc1[k * 128 + t];
    float h1 = fmaxf(a, 0.f);
    r0[t] = h1 * Wc2[t * 2 + 0];
    r1[t] = h1 * Wc2[t * 2 + 1];
    __syncthreads();
    for (int off = 64; off > 0; off >>= 1) {
        if (t < off) { r0[t] += r0[t + off]; r1[t] += r1[t + off]; }
        __syncthreads();
    }
    if (t == 0) {
        out[b * 2 + 0] = r0[0] + bc2[0];
        out[b * 2 + 1] = r1[0] + bc2[1];
    }
}

// ---------------- launch ------------------------------------------------------
extern "C" void kernel_launch(void* const* d_in, const int* in_sizes, int n_in,
                              void* d_out, int out_size) {
    (void)in_sizes; (void)n_in; (void)out_size;
    const float* x   = (const float*)d_in[0];
    const int*   ei  = (const int*)d_in[1];       // int32 (JAX x64 disabled)
    const float* We  = (const float*)d_in[2];
    const float* be  = (const float*)d_in[3];
    const float* Wl1 = (const float*)d_in[4];
    const float* bl1 = (const float*)d_in[5];
    const float* Wr1 = (const float*)d_in[6];
    const float* Wl2 = (const float*)d_in[7];
    const float* bl2 = (const float*)d_in[8];
    const float* Wr2 = (const float*)d_in[9];
    // d_in[10..12] (Wlp, blp, Wrp) dead: softmax over a size-1 axis == 1
    const float* Wc1 = (const float*)d_in[13];
    const float* bc1 = (const float*)d_in[14];
    const float* Wc2 = (const float*)d_in[15];
    const float* bc2 = (const float*)d_in[16];
    float* out = (float*)d_out;

    dim3 mma_grid((NN + 127) / 128, 2, BAGS);    // (40, 2, 16)
    dim3 edge_grid((EE + 255) / 256, BAGS);

    k_zero<<<(BAGS * NN + 255) / 256, 256>>>();
    k_cvtx<<<(BAGS * NN * DIN + 255) / 256, 256>>>(x);
    k_cvtwe<<<(256 * 128 + 255) / 256, 256>>>(We);
    k_cvtw4<<<dim3((256 * 256 + 255) / 256, 4), 256>>>(Wl1, Wr1, Wl2, Wr2);
    // CSR
    k_deg<<<edge_grid, 256>>>(ei);
    k_scan<<<BAGS, 1024>>>();
    k_fill<<<edge_grid, 256>>>(ei);
    // encoder
    k_enc<<<mma_grid, 256>>>(be);
    // layer 1: u = h@Wl1 (2-pass bf16) ; v = h@Wr1 + bl1 (3-pass fp32)
    k_layer<1, 2><<<mma_grid, 256>>>(bl1);
    k_agg2<false><<<(BAGS * NN) / 8, 256>>>();
    // layer 2
    k_layer<3, 4><<<mma_grid, 256>>>(bl2);
    k_agg2<true><<<(BAGS * NN) / 8, 256>>>();
    // pool + classify
    k_reduce<<<dim3(20, BAGS), 256>>>();
    k_cls<<<BAGS, 128>>>(Wc1, bc1, Wc2, bc2, out);
}

// round 10
// speedup vs baseline: 2.3054x; 1.3256x over previous
#include <cuda_runtime.h>
#include <cuda_bf16.h>
#include <cstdint>

#define BAGS 16
#define NN   5000
#define EE   160000
#define DE   256
#define DIN  128

// ---------------- scratch (device globals) -----------------------------------
__device__ __align__(16) __nv_bfloat16 g_xh[BAGS*NN*DIN];
__device__ __align__(16) __nv_bfloat16 g_hh[BAGS*NN*DE];    // h, later g1 (bf16)
__device__ __align__(16) __nv_bfloat16 g_ub[BAGS*NN*DE];    // u in bf16 (gathered)
__device__ __align__(16) float g_v [BAGS*NN*DE];
__device__ __align__(16) float g_g2[BAGS*NN*DE];
__device__ float g_emb[BAGS*DE];
// transposed split weights:  Wt[n][k] = W[k][n]   (hi + lo kept: weight-lo is load-bearing)
__device__ __align__(16) __nv_bfloat16 g_weth[DE*DIN], g_wetl[DE*DIN];
__device__ __align__(16) __nv_bfloat16 g_w1h[DE*DE], g_w1l[DE*DE];   // Wl1^T
__device__ __align__(16) __nv_bfloat16 g_w2h[DE*DE], g_w2l[DE*DE];   // Wr1^T
__device__ __align__(16) __nv_bfloat16 g_w3h[DE*DE], g_w3l[DE*DE];   // Wl2^T
__device__ __align__(16) __nv_bfloat16 g_w4h[DE*DE], g_w4l[DE*DE];   // Wr2^T
// CSR
__device__ int g_deg[BAGS*NN], g_rowptr[BAGS*(NN+1)], g_cursor[BAGS*NN], g_col[BAGS*EE];

// ---------------- helpers -----------------------------------------------------
__device__ __forceinline__ uint32_t smem_u32(const void* p) {
    uint32_t a;
    asm("{ .reg .u64 t; cvta.to.shared.u64 t, %1; cvt.u32.u64 %0, t; }" : "=r"(a) : "l"(p));
    return a;
}
__device__ __forceinline__ uint32_t pack_bf16(float v0, float v1) {
    return (uint32_t)__bfloat16_as_ushort(__float2bfloat16(v0)) |
           ((uint32_t)__bfloat16_as_ushort(__float2bfloat16(v1)) << 16);
}
__device__ __forceinline__ float2 bf2f(uint32_t w) {
    __nv_bfloat162 h = *reinterpret_cast<__nv_bfloat162*>(&w);
    return __bfloat1622float2(h);
}

template <int S> __device__ __forceinline__ __nv_bfloat16* wpair(int lo) {
    switch (S) {
        case 0:  return lo ? g_wetl : g_weth;
        case 1:  return lo ? g_w1l : g_w1h;
        case 2:  return lo ? g_w2l : g_w2h;
        case 3:  return lo ? g_w3l : g_w3h;
        default: return lo ? g_w4l : g_w4h;
    }
}

// ---------------- prep kernels ------------------------------------------------
__global__ void k_zero() {
    int i = blockIdx.x * blockDim.x + threadIdx.x;
    if (i < BAGS * NN) g_deg[i] = 0;
    if (i < BAGS * DE) g_emb[i] = 0.f;
}
__global__ void k_cvtx(const float* __restrict__ x) {
    int i = blockIdx.x * blockDim.x + threadIdx.x;
    if (i >= BAGS * NN * DIN) return;
    g_xh[i] = __float2bfloat16(x[i]);
}
__global__ void k_cvtwe(const float* __restrict__ W) {
    int i = blockIdx.x * blockDim.x + threadIdx.x;
    if (i >= 256 * 128) return;
    int n = i >> 7, k = i & 127;
    float v = W[k * 256 + n];
    __nv_bfloat16 h = __float2bfloat16(v);
    g_weth[i] = h;
    g_wetl[i] = __float2bfloat16(v - __bfloat162float(h));
}
__global__ void k_cvtw4(const float* __restrict__ W1, const float* __restrict__ W2,
                        const float* __restrict__ W3, const float* __restrict__ W4) {
    int i = blockIdx.x * blockDim.x + threadIdx.x;
    if (i >= 256 * 256) return;
    int w = blockIdx.y;
    const float* W = (w == 0) ? W1 : (w == 1) ? W2 : (w == 2) ? W3 : W4;
    __nv_bfloat16* Oh = (w == 0) ? g_w1h : (w == 1) ? g_w2h : (w == 2) ? g_w3h : g_w4h;
    __nv_bfloat16* Ol = (w == 0) ? g_w1l : (w == 1) ? g_w2l : (w == 2) ? g_w3l : g_w4l;
    int n = i >> 8, k = i & 255;
    float v = W[k * 256 + n];
    __nv_bfloat16 h = __float2bfloat16(v);
    Oh[i] = h;
    Ol[i] = __float2bfloat16(v - __bfloat162float(h));
}

// ---------------- CSR build ---------------------------------------------------
__global__ void k_deg(const int* __restrict__ ei) {
    int e = blockIdx.x * blockDim.x + threadIdx.x;
    int b = blockIdx.y;
    if (e >= EE) return;
    int dst = ei[(size_t)b * 2 * EE + EE + e];
    if ((unsigned)dst >= NN) return;
    atomicAdd(&g_deg[b * NN + dst], 1);
}
__global__ void k_scan() {
    int b = blockIdx.x, t = threadIdx.x;
    __shared__ int sh[1024];
    int carry = 0;
    for (int c = 0; c < 5; c++) {
        int idx = c * 1024 + t;
        int v = (idx < NN) ? g_deg[b * NN + idx] : 0;
        sh[t] = v;
        __syncthreads();
        for (int off = 1; off < 1024; off <<= 1) {
            int add = (t >= off) ? sh[t - off] : 0;
            __syncthreads();
            sh[t] += add;
            __syncthreads();
        }
        int excl = sh[t] - v;
        if (idx < NN) {
            g_rowptr[b * (NN + 1) + idx] = carry + excl;
            g_cursor[b * NN + idx] = carry + excl;
        }
        int tot = sh[1023];
        __syncthreads();
        carry += tot;
    }
    if (t == 0) g_rowptr[b * (NN + 1) + NN] = carry;
}
__global__ void k_fill(const int* __restrict__ ei) {
    int e = blockIdx.x * blockDim.x + threadIdx.x;
    int b = blockIdx.y;
    if (e >= EE) return;
    int src = ei[(size_t)b * 2 * EE + e];
    int dst = ei[(size_t)b * 2 * EE + EE + e];
    if ((unsigned)dst >= NN || (unsigned)src >= NN) return;
    int p = atomicAdd(&g_cursor[b * NN + dst], 1);
    g_col[b * EE + p] = src;
}

// ---------------- shared GEMM machinery ---------------------------------------
#define PITCH 80

__device__ __forceinline__ void issue_chunk(
    const __nv_bfloat16* __restrict__ Agl, const __nv_bfloat16* __restrict__ Bgl,
    int KD, int m0, int kc, char* sA, char* sB, int tid)
{
    #pragma unroll
    for (int v = 0; v < 2; v++) {
        int idx = v * 256 + tid;
        int row = idx >> 2, c16 = idx & 3;
        int gr = m0 + row;
        const void* src = Agl + (size_t)gr * KD + kc + c16 * 8;
        uint32_t dst = smem_u32(sA + row * PITCH + c16 * 16);
        int sz = (gr < NN) ? 16 : 0;
        asm volatile("cp.async.cg.shared.global [%0], [%1], 16, %2;"
                     :: "r"(dst), "l"(src), "r"(sz));
    }
    #pragma unroll
    for (int v = 0; v < 2; v++) {
        int idx = v * 256 + tid;
        int row = idx >> 2, c16 = idx & 3;
        const void* src = Bgl + (size_t)row * KD + kc + c16 * 8;
        uint32_t dst = smem_u32(sB + row * PITCH + c16 * 16);
        asm volatile("cp.async.cg.shared.global [%0], [%1], 16;"
                     :: "r"(dst), "l"(src));
    }
    asm volatile("cp.async.commit_group;");
}

__device__ __forceinline__ void mma_chunk(const char* sA, const char* sB,
                                          int wm, int wn, int lane, float acc[4][4][4]) {
    #pragma unroll
    for (int ks = 0; ks < 2; ks++) {
        uint32_t afr[4][4];
        #pragma unroll
        for (int mi = 0; mi < 4; mi++) {
            uint32_t ad = smem_u32(sA + (wm * 64 + mi * 16 + (lane & 15)) * PITCH
                                      + ks * 32 + (lane >> 4) * 16);
            asm volatile("ldmatrix.sync.aligned.m8n8.x4.shared.b16 {%0,%1,%2,%3}, [%4];"
                         : "=r"(afr[mi][0]), "=r"(afr[mi][1]),
                           "=r"(afr[mi][2]), "=r"(afr[mi][3]) : "r"(ad));
        }
        uint32_t bfr[4][2];
        #pragma unroll
        for (int q = 0; q < 2; q++) {
            int g = lane >> 3;
            uint32_t bd = smem_u32(sB + (wn * 32 + q * 16 + (g >> 1) * 8 + (lane & 7)) * PITCH
                                      + ks * 32 + (g & 1) * 16);
            asm volatile("ldmatrix.sync.aligned.m8n8.x4.shared.b16 {%0,%1,%2,%3}, [%4];"
                         : "=r"(bfr[2 * q][0]), "=r"(bfr[2 * q][1]),
                           "=r"(bfr[2 * q + 1][0]), "=r"(bfr[2 * q + 1][1]) : "r"(bd));
        }
        #pragma unroll
        for (int mi = 0; mi < 4; mi++)
            #pragma unroll
            for (int ni = 0; ni < 4; ni++)
                asm volatile(
                    "mma.sync.aligned.m16n8k16.row.col.f32.bf16.bf16.f32 "
                    "{%0,%1,%2,%3}, {%4,%5,%6,%7}, {%8,%9}, {%0,%1,%2,%3};"
                    : "+f"(acc[mi][ni][0]), "+f"(acc[mi][ni][1]),
                      "+f"(acc[mi][ni][2]), "+f"(acc[mi][ni][3])
                    : "r"(afr[mi][0]), "r"(afr[mi][1]), "r"(afr[mi][2]), "r"(afr[mi][3]),
                      "r"(bfr[ni][0]), "r"(bfr[ni][1]));
    }
}

// ---------------- encoder GEMM: h = relu(x@We + be) -> bf16 -------------------
// 2-pass: xh*Weh + xh*Wel (activation-lo dropped: node-decorrelated error only)
__global__ void __launch_bounds__(256, 2) k_enc(const float* __restrict__ bias) {
    __shared__ __align__(16) char smA[2][128 * PITCH];
    __shared__ __align__(16) char smB[2][128 * PITCH];
    const int KD = DIN;
    int tid = threadIdx.x, lane = tid & 31, warp = tid >> 5;
    int wm = warp & 1, wn = warp >> 1;
    int m0 = blockIdx.x * 128, n0 = blockIdx.y * 128, b = blockIdx.z;

    const __nv_bfloat16* Ah = g_xh + (size_t)b * NN * KD;
    const __nv_bfloat16* Bh = g_weth + (size_t)n0 * KD;
    const __nv_bfloat16* Bl = g_wetl + (size_t)n0 * KD;

    const int NCH = KD / 32, TOT = 2 * NCH;
    float acc[4][4][4] = {};
    #define BPE(it) ((it) < NCH ? Bh : Bl)
    issue_chunk(Ah, BPE(0), KD, m0, 0, smA[0], smB[0], tid);
    issue_chunk(Ah, BPE(1), KD, m0, (1 % NCH) * 32, smA[1], smB[1], tid);
    for (int it = 0; it < TOT; it++) {
        if (it + 1 < TOT) asm volatile("cp.async.wait_group 1;");
        else              asm volatile("cp.async.wait_group 0;");
        __syncthreads();
        mma_chunk(smA[it & 1], smB[it & 1], wm, wn, lane, acc);
        __syncthreads();
        if (it + 2 < TOT)
            issue_chunk(Ah, BPE(it + 2), KD, m0, ((it + 2) % NCH) * 32,
                        smA[it & 1], smB[it & 1], tid);
    }
    #undef BPE

    #pragma unroll
    for (int mi = 0; mi < 4; mi++)
        #pragma unroll
        for (int ni = 0; ni < 4; ni++) {
            int r0 = m0 + wm * 64 + mi * 16 + (lane >> 2);
            int c0 = n0 + wn * 32 + ni * 8 + (lane & 3) * 2;
            float b0 = __ldg(&bias[c0]), b1 = __ldg(&bias[c0 + 1]);
            float v00 = fmaxf(acc[mi][ni][0] + b0, 0.f), v01 = fmaxf(acc[mi][ni][1] + b1, 0.f);
            float v10 = fmaxf(acc[mi][ni][2] + b0, 0.f), v11 = fmaxf(acc[mi][ni][3] + b1, 0.f);
            if (r0 < NN)
                *(uint32_t*)&g_hh[((size_t)b * NN + r0) * DE + c0] = pack_bf16(v00, v01);
            if (r0 + 8 < NN)
                *(uint32_t*)&g_hh[((size_t)b * NN + r0 + 8) * DE + c0] = pack_bf16(v10, v11);
        }
}

// ---------------- merged layer GEMM kernel ------------------------------------
// u (2 pass): u = h@Wl -> bf16 g_ub     chunks [0,2N)   (Ah*WLh, Ah*WLl)
// v (2 pass): v = h@Wr + bias -> fp32   chunks [2N,4N)  (Ah*WRh, Ah*WRl)
// all activation-lo terms dropped (node-decorrelated); weight-lo kept.
template <int WLSEL, int WRSEL>
__global__ void __launch_bounds__(256, 2) k_layer(const float* __restrict__ bias) {
    __shared__ __align__(16) char smA[2][128 * PITCH];
    __shared__ __align__(16) char smB[2][128 * PITCH];
    const int KD = DE;
    int tid = threadIdx.x, lane = tid & 31, warp = tid >> 5;
    int wm = warp & 1, wn = warp >> 1;
    int m0 = blockIdx.x * 128, n0 = blockIdx.y * 128, b = blockIdx.z;

    const __nv_bfloat16* Ah  = g_hh + (size_t)b * NN * KD;
    const __nv_bfloat16* WLh = wpair<WLSEL>(0) + (size_t)n0 * KD;
    const __nv_bfloat16* WLl = wpair<WLSEL>(1) + (size_t)n0 * KD;
    const __nv_bfloat16* WRh = wpair<WRSEL>(0) + (size_t)n0 * KD;
    const __nv_bfloat16* WRl = wpair<WRSEL>(1) + (size_t)n0 * KD;

    const int NCH = KD / 32, TOT = 4 * NCH;
    float acc[4][4][4] = {};
    #define BPL(it) ((it) < NCH ? WLh : ((it) < 2 * NCH ? WLl : \
                     ((it) < 3 * NCH ? WRh : WRl)))
    issue_chunk(Ah, BPL(0), KD, m0, 0, smA[0], smB[0], tid);
    issue_chunk(Ah, BPL(1), KD, m0, (1 % NCH) * 32, smA[1], smB[1], tid);
    for (int it = 0; it < TOT; it++) {
        if (it + 1 < TOT) asm volatile("cp.async.wait_group 1;");
        else              asm volatile("cp.async.wait_group 0;");
        __syncthreads();
        mma_chunk(smA[it & 1], smB[it & 1], wm, wn, lane, acc);
        __syncthreads();
        if (it + 2 < TOT)
            issue_chunk(Ah, BPL(it + 2), KD, m0, ((it + 2) % NCH) * 32,
                        smA[it & 1], smB[it & 1], tid);
        if (it == 2 * NCH - 1) {
            // u complete: write bf16, reset accumulators
            #pragma unroll
            for (int mi = 0; mi < 4; mi++)
                #pragma unroll
                for (int ni = 0; ni < 4; ni++) {
                    int r0 = m0 + wm * 64 + mi * 16 + (lane >> 2);
                    int c0 = n0 + wn * 32 + ni * 8 + (lane & 3) * 2;
                    if (r0 < NN)
                        *(uint32_t*)&g_ub[((size_t)b * NN + r0) * DE + c0] =
                            pack_bf16(acc[mi][ni][0], acc[mi][ni][1]);
                    if (r0 + 8 < NN)
                        *(uint32_t*)&g_ub[((size_t)b * NN + r0 + 8) * DE + c0] =
                            pack_bf16(acc[mi][ni][2], acc[mi][ni][3]);
                    acc[mi][ni][0] = acc[mi][ni][1] = acc[mi][ni][2] = acc[mi][ni][3] = 0.f;
                }
        }
    }
    #undef BPL

    // v epilogue (+bias, fp32)
    #pragma unroll
    for (int mi = 0; mi < 4; mi++)
        #pragma unroll
        for (int ni = 0; ni < 4; ni++) {
            int r0 = m0 + wm * 64 + mi * 16 + (lane >> 2);
            int c0 = n0 + wn * 32 + ni * 8 + (lane & 3) * 2;
            float b0 = __ldg(&bias[c0]), b1 = __ldg(&bias[c0 + 1]);
            if (r0 < NN)
                *(float2*)&g_v[((size_t)b * NN + r0) * DE + c0] =
                    make_float2(acc[mi][ni][0] + b0, acc[mi][ni][1] + b1);
            if (r0 + 8 < NN)
                *(float2*)&g_v[((size_t)b * NN + r0 + 8) * DE + c0] =
                    make_float2(acc[mi][ni][2] + b0, acc[mi][ni][3] + b1);
        }
}

// ---------------- fused SAGE combine: g = relu(mean_e(U) + V) -----------------
template <bool FINAL>
__global__ void k_agg2() {
    int w = (blockIdx.x * blockDim.x + threadIdx.x) >> 5;
    int lane = threadIdx.x & 31;
    if (w >= BAGS * NN) return;
    int b = w / NN, i = w - b * NN;
    int r0 = g_rowptr[b * (NN + 1) + i];
    int r1 = g_rowptr[b * (NN + 1) + i + 1];
    const __nv_bfloat16* Ub = g_ub + (size_t)b * NN * DE;
    const int* colb = g_col + b * EE;
    float a[8] = {0.f, 0.f, 0.f, 0.f, 0.f, 0.f, 0.f, 0.f};
    for (int e = r0; e < r1; e++) {
        int s = __ldg(&colb[e]);
        uint4 r = __ldg((const uint4*)(Ub + (size_t)s * DE) + lane);
        float2 p0 = bf2f(r.x), p1 = bf2f(r.y), p2 = bf2f(r.z), p3 = bf2f(r.w);
        a[0] += p0.x; a[1] += p0.y; a[2] += p1.x; a[3] += p1.y;
        a[4] += p2.x; a[5] += p2.y; a[6] += p3.x; a[7] += p3.y;
    }
    int dg = r1 - r0;
    float inv = 1.f / (float)(dg > 1 ? dg : 1);
    size_t base = ((size_t)b * NN + i) * DE + lane * 8;
    float4 v0 = *(const float4*)(g_v + base);
    float4 v1 = *(const float4*)(g_v + base + 4);
    float g[8];
    g[0] = fmaxf(a[0] * inv + v0.x, 0.f); g[1] = fmaxf(a[1] * inv + v0.y, 0.f);
    g[2] = fmaxf(a[2] * inv + v0.z, 0.f); g[3] = fmaxf(a[3] * inv + v0.w, 0.f);
    g[4] = fmaxf(a[4] * inv + v1.x, 0.f); g[5] = fmaxf(a[5] * inv + v1.y, 0.f);
    g[6] = fmaxf(a[6] * inv + v1.z, 0.f); g[7] = fmaxf(a[7] * inv + v1.w, 0.f);
    if (!FINAL) {
        uint32_t hp[4];
        #pragma unroll
        for (int q = 0; q < 4; q++) hp[q] = pack_bf16(g[2 * q], g[2 * q + 1]);
        *(uint4*)(&g_hh[base]) = *(uint4*)hp;
    } else {
        *(float4*)(&g_g2[base])     = make_float4(g[0], g[1], g[2], g[3]);
        *(float4*)(&g_g2[base + 4]) = make_float4(g[4], g[5], g[6], g[7]);
    }
}

// ---------------- pooled embedding + classifier -------------------------------
__global__ void k_reduce() {
    int b = blockIdx.y, c = threadIdx.x;
    int i0 = blockIdx.x * 250, i1 = i0 + 250;
    const float* Gb = g_g2 + (size_t)b * NN * DE;
    float s = 0.f;
    for (int i = i0; i < i1; i++) s += Gb[(size_t)i * DE + c];
    atomicAdd(&g_emb[b * DE + c], s);
}
__global__ void k_cls(const float* __restrict__ Wc1, const float* __restrict__ bc1,
                      const float* __restrict__ Wc2, const float* __restrict__ bc2,
                      float* __restrict__ out) {
    int b = blockIdx.x, t = threadIdx.x;   // 128 threads
    __shared__ float es[256];
    __shared__ float r0[128], r1[128];
    es[t]       = g_emb[b * DE + t];
    es[t + 128] = g_emb[b * DE + t + 128];
    __syncthreads();
    float a = bc1[t];
    #pragma unroll 8
    for (int k = 0; k < 256; k++) a += es[k] * Wc1[k * 128 + t];
    float h1 = fmaxf(a, 0.f);
    r0[t] = h1 * Wc2[t * 2 + 0];
    r1[t] = h1 * Wc2[t * 2 + 1];
    __syncthreads();
    for (int off = 64; off > 0; off >>= 1) {
        if (t < off) { r0[t] += r0[t + off]; r1[t] += r1[t + off]; }
        __syncthreads();
    }
    if (t == 0) {
        out[b * 2 + 0] = r0[0] + bc2[0];
        out[b * 2 + 1] = r1[0] + bc2[1];
    }
}

// ---------------- launch ------------------------------------------------------
extern "C" void kernel_launch(void* const* d_in, const int* in_sizes, int n_in,
                              void* d_out, int out_size) {
    (void)in_sizes; (void)n_in; (void)out_size;
    const float* x   = (const float*)d_in[0];
    const int*   ei  = (const int*)d_in[1];       // int32 (JAX x64 disabled)
    const float* We  = (const float*)d_in[2];
    const float* be  = (const float*)d_in[3];
    const float* Wl1 = (const float*)d_in[4];
    const float* bl1 = (const float*)d_in[5];
    const float* Wr1 = (const float*)d_in[6];
    const float* Wl2 = (const float*)d_in[7];
    const float* bl2 = (const float*)d_in[8];
    const float* Wr2 = (const float*)d_in[9];
    // d_in[10..12] (Wlp, blp, Wrp) dead: softmax over a size-1 axis == 1
    const float* Wc1 = (const float*)d_in[13];
    const float* bc1 = (const float*)d_in[14];
    const float* Wc2 = (const float*)d_in[15];
    const float* bc2 = (const float*)d_in[16];
    float* out = (float*)d_out;

    dim3 mma_grid((NN + 127) / 128, 2, BAGS);    // (40, 2, 16)
    dim3 edge_grid((EE + 255) / 256, BAGS);

    k_zero<<<(BAGS * NN + 255) / 256, 256>>>();
    k_cvtx<<<(BAGS * NN * DIN + 255) / 256, 256>>>(x);
    k_cvtwe<<<(256 * 128 + 255) / 256, 256>>>(We);
    k_cvtw4<<<dim3((256 * 256 + 255) / 256, 4), 256>>>(Wl1, Wr1, Wl2, Wr2);
    // CSR
    k_deg<<<edge_grid, 256>>>(ei);
    k_scan<<<BAGS, 1024>>>();
    k_fill<<<edge_grid, 256>>>(ei);
    // encoder
    k_enc<<<mma_grid, 256>>>(be);
    // layer 1
    k_layer<1, 2><<<mma_grid, 256>>>(bl1);
    k_agg2<false><<<(BAGS * NN) / 8, 256>>>();
    // layer 2
    k_layer<3, 4><<<mma_grid, 256>>>(bl2);
    k_agg2<true><<<(BAGS * NN) / 8, 256>>>();
    // pool + classify
    k_reduce<<<dim3(20, BAGS), 256>>>();
    k_cls<<<BAGS, 128>>>(Wc1, bc1, Wc2, bc2, out);
}

// round 11
// speedup vs baseline: 3.1189x; 1.3529x over previous
#include <cuda_runtime.h>
#include <cuda_fp16.h>
#include <cstdint>

#define BAGS 16
#define NN   5000
#define EE   160000
#define DE   256
#define DIN  128

// ---------------- scratch (device globals) -----------------------------------
__device__ __align__(16) __half g_x [BAGS*NN*DIN];
__device__ __align__(16) __half g_h [BAGS*NN*DE];     // h, later g1
__device__ __align__(16) __half g_u [BAGS*NN*DE];     // u (gathered)
__device__ __align__(16) __half g_v [BAGS*NN*DE];
__device__ __align__(16) float  g_g2[BAGS*NN*DE];
__device__ float g_emb[BAGS*DE];
// transposed fp16 weights: Wt[n][k] = W[k][n]  (single copy — fp16 mantissa suffices)
__device__ __align__(16) __half g_we[DE*DIN];
__device__ __align__(16) __half g_w1[DE*DE], g_w2[DE*DE], g_w3[DE*DE], g_w4[DE*DE];
// CSR
__device__ int g_deg[BAGS*NN], g_rowptr[BAGS*(NN+1)], g_cursor[BAGS*NN], g_col[BAGS*EE];

// ---------------- helpers -----------------------------------------------------
__device__ __forceinline__ uint32_t smem_u32(const void* p) {
    uint32_t a;
    asm("{ .reg .u64 t; cvta.to.shared.u64 t, %1; cvt.u32.u64 %0, t; }" : "=r"(a) : "l"(p));
    return a;
}
__device__ __forceinline__ uint32_t pack_h2(float v0, float v1) {
    __half2 h = __floats2half2_rn(v0, v1);
    return *reinterpret_cast<uint32_t*>(&h);
}
template <int S> __device__ __forceinline__ const __half* wsel() {
    switch (S) {
        case 0:  return g_we;
        case 1:  return g_w1;
        case 2:  return g_w2;
        case 3:  return g_w3;
        default: return g_w4;
    }
}

// ---------------- prep --------------------------------------------------------
__global__ void k_zero() {
    int i = blockIdx.x * blockDim.x + threadIdx.x;
    if (i < BAGS * NN) g_deg[i] = 0;
    if (i < BAGS * DE) g_emb[i] = 0.f;
}
#define P_DEG (BAGS*EE)
#define P_X   (BAGS*NN*DIN)
#define P_WE  (DE*DIN)
#define P_W4  (4*DE*DE)
#define P_TOT (P_DEG + P_X + P_WE + P_W4)
// one flat kernel: edge-degree histogram + all fp32->fp16 conversions
__global__ void k_prep(const float* __restrict__ x, const int* __restrict__ ei,
                       const float* __restrict__ We, const float* __restrict__ W1,
                       const float* __restrict__ W2, const float* __restrict__ W3,
                       const float* __restrict__ W4) {
    int idx = blockIdx.x * blockDim.x + threadIdx.x;
    if (idx < P_DEG) {
        int b = idx / EE, e = idx - b * EE;
        int dst = ei[(size_t)b * 2 * EE + EE + e];
        if ((unsigned)dst < NN) atomicAdd(&g_deg[b * NN + dst], 1);
        return;
    }
    idx -= P_DEG;
    if (idx < P_X) { g_x[idx] = __float2half_rn(x[idx]); return; }
    idx -= P_X;
    if (idx < P_WE) {
        int n = idx >> 7, k = idx & 127;
        g_we[idx] = __float2half_rn(We[k * DE + n]);
        return;
    }
    idx -= P_WE;
    if (idx < P_W4) {
        int w = idx >> 16, j = idx & 65535;
        const float* W = (w == 0) ? W1 : (w == 1) ? W2 : (w == 2) ? W3 : W4;
        __half* O = (w == 0) ? g_w1 : (w == 1) ? g_w2 : (w == 2) ? g_w3 : g_w4;
        int n = j >> 8, k = j & 255;
        O[j] = __float2half_rn(W[k * DE + n]);
    }
}

// ---------------- CSR scan + fill ---------------------------------------------
__global__ void k_scan() {
    int b = blockIdx.x, t = threadIdx.x;
    __shared__ int sh[1024];
    int carry = 0;
    for (int c = 0; c < 5; c++) {
        int idx = c * 1024 + t;
        int v = (idx < NN) ? g_deg[b * NN + idx] : 0;
        sh[t] = v;
        __syncthreads();
        for (int off = 1; off < 1024; off <<= 1) {
            int add = (t >= off) ? sh[t - off] : 0;
            __syncthreads();
            sh[t] += add;
            __syncthreads();
        }
        int excl = sh[t] - v;
        if (idx < NN) {
            g_rowptr[b * (NN + 1) + idx] = carry + excl;
            g_cursor[b * NN + idx] = carry + excl;
        }
        int tot = sh[1023];
        __syncthreads();
        carry += tot;
    }
    if (t == 0) g_rowptr[b * (NN + 1) + NN] = carry;
}
__global__ void k_fill(const int* __restrict__ ei) {
    int e = blockIdx.x * blockDim.x + threadIdx.x;
    int b = blockIdx.y;
    if (e >= EE) return;
    int src = ei[(size_t)b * 2 * EE + e];
    int dst = ei[(size_t)b * 2 * EE + EE + e];
    if ((unsigned)dst >= NN || (unsigned)src >= NN) return;
    int p = atomicAdd(&g_cursor[b * NN + dst], 1);
    g_col[b * EE + p] = src;
}

// ---------------- GEMM machinery ----------------------------------------------
#define PITCH 80

__device__ __forceinline__ void issue_chunk(
    const __half* __restrict__ Agl, const __half* __restrict__ Bgl,
    int KD, int m0, int kc, char* sA, char* sB, int tid)
{
    #pragma unroll
    for (int v = 0; v < 2; v++) {
        int idx = v * 256 + tid;
        int row = idx >> 2, c16 = idx & 3;
        int gr = m0 + row;
        const void* src = Agl + (size_t)gr * KD + kc + c16 * 8;
        uint32_t dst = smem_u32(sA + row * PITCH + c16 * 16);
        int sz = (gr < NN) ? 16 : 0;
        asm volatile("cp.async.cg.shared.global [%0], [%1], 16, %2;"
                     :: "r"(dst), "l"(src), "r"(sz));
    }
    #pragma unroll
    for (int v = 0; v < 2; v++) {
        int idx = v * 256 + tid;
        int row = idx >> 2, c16 = idx & 3;
        const void* src = Bgl + (size_t)row * KD + kc + c16 * 8;
        uint32_t dst = smem_u32(sB + row * PITCH + c16 * 16);
        asm volatile("cp.async.cg.shared.global [%0], [%1], 16;"
                     :: "r"(dst), "l"(src));
    }
    asm volatile("cp.async.commit_group;");
}

__device__ __forceinline__ void mma_chunk(const char* sA, const char* sB,
                                          int wm, int wn, int lane, float acc[4][4][4]) {
    #pragma unroll
    for (int ks = 0; ks < 2; ks++) {
        uint32_t afr[4][4];
        #pragma unroll
        for (int mi = 0; mi < 4; mi++) {
            uint32_t ad = smem_u32(sA + (wm * 64 + mi * 16 + (lane & 15)) * PITCH
                                      + ks * 32 + (lane >> 4) * 16);
            asm volatile("ldmatrix.sync.aligned.m8n8.x4.shared.b16 {%0,%1,%2,%3}, [%4];"
                         : "=r"(afr[mi][0]), "=r"(afr[mi][1]),
                           "=r"(afr[mi][2]), "=r"(afr[mi][3]) : "r"(ad));
        }
        uint32_t bfr[4][2];
        #pragma unroll
        for (int q = 0; q < 2; q++) {
            int g = lane >> 3;
            uint32_t bd = smem_u32(sB + (wn * 32 + q * 16 + (g >> 1) * 8 + (lane & 7)) * PITCH
                                      + ks * 32 + (g & 1) * 16);
            asm volatile("ldmatrix.sync.aligned.m8n8.x4.shared.b16 {%0,%1,%2,%3}, [%4];"
                         : "=r"(bfr[2 * q][0]), "=r"(bfr[2 * q][1]),
                           "=r"(bfr[2 * q + 1][0]), "=r"(bfr[2 * q + 1][1]) : "r"(bd));
        }
        #pragma unroll
        for (int mi = 0; mi < 4; mi++)
            #pragma unroll
            for (int ni = 0; ni < 4; ni++)
                asm volatile(
                    "mma.sync.aligned.m16n8k16.row.col.f32.f16.f16.f32 "
                    "{%0,%1,%2,%3}, {%4,%5,%6,%7}, {%8,%9}, {%0,%1,%2,%3};"
                    : "+f"(acc[mi][ni][0]), "+f"(acc[mi][ni][1]),
                      "+f"(acc[mi][ni][2]), "+f"(acc[mi][ni][3])
                    : "r"(afr[mi][0]), "r"(afr[mi][1]), "r"(afr[mi][2]), "r"(afr[mi][3]),
                      "r"(bfr[ni][0]), "r"(bfr[ni][1]));
    }
}

// ---------------- encoder: h = relu(x@We + be) -> fp16 (single pass) ----------
__global__ void __launch_bounds__(256, 2) k_enc(const float* __restrict__ bias) {
    __shared__ __align__(16) char smA[2][128 * PITCH];
    __shared__ __align__(16) char smB[2][128 * PITCH];
    const int KD = DIN;
    int tid = threadIdx.x, lane = tid & 31, warp = tid >> 5;
    int wm = warp & 1, wn = warp >> 1;
    int m0 = blockIdx.x * 128, n0 = blockIdx.y * 128, b = blockIdx.z;

    const __half* Ah = g_x + (size_t)b * NN * KD;
    const __half* Bh = g_we + (size_t)n0 * KD;

    const int TOT = KD / 32;                    // 4 chunks
    float acc[4][4][4] = {};
    issue_chunk(Ah, Bh, KD, m0, 0, smA[0], smB[0], tid);
    issue_chunk(Ah, Bh, KD, m0, 32, smA[1], smB[1], tid);
    for (int it = 0; it < TOT; it++) {
        if (it + 1 < TOT) asm volatile("cp.async.wait_group 1;");
        else              asm volatile("cp.async.wait_group 0;");
        __syncthreads();
        mma_chunk(smA[it & 1], smB[it & 1], wm, wn, lane, acc);
        __syncthreads();
        if (it + 2 < TOT)
            issue_chunk(Ah, Bh, KD, m0, (it + 2) * 32, smA[it & 1], smB[it & 1], tid);
    }

    #pragma unroll
    for (int mi = 0; mi < 4; mi++)
        #pragma unroll
        for (int ni = 0; ni < 4; ni++) {
            int r0 = m0 + wm * 64 + mi * 16 + (lane >> 2);
            int c0 = n0 + wn * 32 + ni * 8 + (lane & 3) * 2;
            float b0 = __ldg(&bias[c0]), b1 = __ldg(&bias[c0 + 1]);
            float v00 = fmaxf(acc[mi][ni][0] + b0, 0.f), v01 = fmaxf(acc[mi][ni][1] + b1, 0.f);
            float v10 = fmaxf(acc[mi][ni][2] + b0, 0.f), v11 = fmaxf(acc[mi][ni][3] + b1, 0.f);
            if (r0 < NN)
                *(uint32_t*)&g_h[((size_t)b * NN + r0) * DE + c0] = pack_h2(v00, v01);
            if (r0 + 8 < NN)
                *(uint32_t*)&g_h[((size_t)b * NN + r0 + 8) * DE + c0] = pack_h2(v10, v11);
        }
}

// ---------------- layer GEMM: u = h@Wl (fp16), v = h@Wr + bias (fp16) ---------
template <int WLSEL, int WRSEL>
__global__ void __launch_bounds__(256, 2) k_layer(const float* __restrict__ bias) {
    __shared__ __align__(16) char smA[2][128 * PITCH];
    __shared__ __align__(16) char smB[2][128 * PITCH];
    const int KD = DE;
    int tid = threadIdx.x, lane = tid & 31, warp = tid >> 5;
    int wm = warp & 1, wn = warp >> 1;
    int m0 = blockIdx.x * 128, n0 = blockIdx.y * 128, b = blockIdx.z;

    const __half* Ah = g_h + (size_t)b * NN * KD;
    const __half* WL = wsel<WLSEL>() + (size_t)n0 * KD;
    const __half* WR = wsel<WRSEL>() + (size_t)n0 * KD;

    const int NCH = KD / 32, TOT = 2 * NCH;     // 8 + 8
    float acc[4][4][4] = {};
    #define BPL(it) ((it) < NCH ? WL : WR)
    issue_chunk(Ah, BPL(0), KD, m0, 0, smA[0], smB[0], tid);
    issue_chunk(Ah, BPL(1), KD, m0, (1 % NCH) * 32, smA[1], smB[1], tid);
    for (int it = 0; it < TOT; it++) {
        if (it + 1 < TOT) asm volatile("cp.async.wait_group 1;");
        else              asm volatile("cp.async.wait_group 0;");
        __syncthreads();
        mma_chunk(smA[it & 1], smB[it & 1], wm, wn, lane, acc);
        __syncthreads();
        if (it + 2 < TOT)
            issue_chunk(Ah, BPL(it + 2), KD, m0, ((it + 2) % NCH) * 32,
                        smA[it & 1], smB[it & 1], tid);
        if (it == NCH - 1) {
            // u complete: write fp16, reset accumulators
            #pragma unroll
            for (int mi = 0; mi < 4; mi++)
                #pragma unroll
                for (int ni = 0; ni < 4; ni++) {
                    int r0 = m0 + wm * 64 + mi * 16 + (lane >> 2);
                    int c0 = n0 + wn * 32 + ni * 8 + (lane & 3) * 2;
                    if (r0 < NN)
                        *(uint32_t*)&g_u[((size_t)b * NN + r0) * DE + c0] =
                            pack_h2(acc[mi][ni][0], acc[mi][ni][1]);
                    if (r0 + 8 < NN)
                        *(uint32_t*)&g_u[((size_t)b * NN + r0 + 8) * DE + c0] =
                            pack_h2(acc[mi][ni][2], acc[mi][ni][3]);
                    acc[mi][ni][0] = acc[mi][ni][1] = acc[mi][ni][2] = acc[mi][ni][3] = 0.f;
                }
        }
    }
    #undef BPL

    // v epilogue (+bias, fp16)
    #pragma unroll
    for (int mi = 0; mi < 4; mi++)
        #pragma unroll
        for (int ni = 0; ni < 4; ni++) {
            int r0 = m0 + wm * 64 + mi * 16 + (lane >> 2);
            int c0 = n0 + wn * 32 + ni * 8 + (lane & 3) * 2;
            float b0 = __ldg(&bias[c0]), b1 = __ldg(&bias[c0 + 1]);
            if (r0 < NN)
                *(uint32_t*)&g_v[((size_t)b * NN + r0) * DE + c0] =
                    pack_h2(acc[mi][ni][0] + b0, acc[mi][ni][1] + b1);
            if (r0 + 8 < NN)
                *(uint32_t*)&g_v[((size_t)b * NN + r0 + 8) * DE + c0] =
                    pack_h2(acc[mi][ni][2] + b0, acc[mi][ni][3] + b1);
        }
}

// ---------------- fused SAGE combine: g = relu(mean_e(U) + V) -----------------
// packed HADD2 f16x2 accumulation: 4 ops per 8 channels, zero conversions.
template <bool FINAL>
__global__ void k_agg2() {
    int w = (blockIdx.x * blockDim.x + threadIdx.x) >> 5;
    int lane = threadIdx.x & 31;
    if (w >= BAGS * NN) return;
    int b = w / NN, i = w - b * NN;
    int r0 = g_rowptr[b * (NN + 1) + i];
    int r1 = g_rowptr[b * (NN + 1) + i + 1];
    const __half* Ub = g_u + (size_t)b * NN * DE;
    const int* colb = g_col + b * EE;
    __half2 a0 = __floats2half2_rn(0.f, 0.f), a1 = a0, a2 = a0, a3 = a0;
    for (int e = r0; e < r1; e++) {
        int s = __ldg(&colb[e]);
        uint4 r = __ldg((const uint4*)(Ub + (size_t)s * DE) + lane);
        a0 = __hadd2(a0, *reinterpret_cast<__half2*>(&r.x));
        a1 = __hadd2(a1, *reinterpret_cast<__half2*>(&r.y));
        a2 = __hadd2(a2, *reinterpret_cast<__half2*>(&r.z));
        a3 = __hadd2(a3, *reinterpret_cast<__half2*>(&r.w));
    }
    int dg = r1 - r0;
    float inv = 1.f / (float)(dg > 1 ? dg : 1);
    size_t base = ((size_t)b * NN + i) * DE + lane * 8;
    uint4 rv = *(const uint4*)(g_v + base);
    float2 f0 = __half22float2(a0), f1 = __half22float2(a1);
    float2 f2 = __half22float2(a2), f3 = __half22float2(a3);
    float2 v0 = __half22float2(*reinterpret_cast<__half2*>(&rv.x));
    float2 v1 = __half22float2(*reinterpret_cast<__half2*>(&rv.y));
    float2 v2 = __half22float2(*reinterpret_cast<__half2*>(&rv.z));
    float2 v3 = __half22float2(*reinterpret_cast<__half2*>(&rv.w));
    float g[8];
    g[0] = fmaxf(f0.x * inv + v0.x, 0.f); g[1] = fmaxf(f0.y * inv + v0.y, 0.f);
    g[2] = fmaxf(f1.x * inv + v1.x, 0.f); g[3] = fmaxf(f1.y * inv + v1.y, 0.f);
    g[4] = fmaxf(f2.x * inv + v2.x, 0.f); g[5] = fmaxf(f2.y * inv + v2.y, 0.f);
    g[6] = fmaxf(f3.x * inv + v3.x, 0.f); g[7] = fmaxf(f3.y * inv + v3.y, 0.f);
    if (!FINAL) {
        uint32_t hp[4];
        #pragma unroll
        for (int q = 0; q < 4; q++) hp[q] = pack_h2(g[2 * q], g[2 * q + 1]);
        *(uint4*)(&g_h[base]) = *(uint4*)hp;
    } else {
        *(float4*)(&g_g2[base])     = make_float4(g[0], g[1], g[2], g[3]);
        *(float4*)(&g_g2[base + 4]) = make_float4(g[4], g[5], g[6], g[7]);
    }
}

// ---------------- pooled embedding + classifier -------------------------------
__global__ void k_reduce() {
    int b = blockIdx.y, c = threadIdx.x;
    int i0 = blockIdx.x * 250, i1 = i0 + 250;
    const float* Gb = g_g2 + (size_t)b * NN * DE;
    float s = 0.f;
    for (int i = i0; i < i1; i++) s += Gb[(size_t)i * DE + c];
    atomicAdd(&g_emb[b * DE + c], s);
}
__global__ void k_cls(const float* __restrict__ Wc1, const float* __restrict__ bc1,
                      const float* __restrict__ Wc2, const float* __restrict__ bc2,
                      float* __restrict__ out) {
    int b = blockIdx.x, t = threadIdx.x;   // 128 threads
    __shared__ float es[256];
    __shared__ float r0[128], r1[128];
    es[t]       = g_emb[b * DE + t];
    es[t + 128] = g_emb[b * DE + t + 128];
    __syncthreads();
    float a = bc1[t];
    #pragma unroll 8
    for (int k = 0; k < 256; k++) a += es[k] * Wc1[k * 128 + t];
    float h1 = fmaxf(a, 0.f);
    r0[t] = h1 * Wc2[t * 2 + 0];
    r1[t] = h1 * Wc2[t * 2 + 1];
    __syncthreads();
    for (int off = 64; off > 0; off >>= 1) {
        if (t < off) { r0[t] += r0[t + off]; r1[t] += r1[t + off]; }
        __syncthreads();
    }
    if (t == 0) {
        out[b * 2 + 0] = r0[0] + bc2[0];
        out[b * 2 + 1] = r1[0] + bc2[1];
    }
}

// ---------------- launch ------------------------------------------------------
extern "C" void kernel_launch(void* const* d_in, const int* in_sizes, int n_in,
                              void* d_out, int out_size) {
    (void)in_sizes; (void)n_in; (void)out_size;
    const float* x   = (const float*)d_in[0];
    const int*   ei  = (const int*)d_in[1];       // int32 (JAX x64 disabled)
    const float* We  = (const float*)d_in[2];
    const float* be  = (const float*)d_in[3];
    const float* Wl1 = (const float*)d_in[4];
    const float* bl1 = (const float*)d_in[5];
    const float* Wr1 = (const float*)d_in[6];
    const float* Wl2 = (const float*)d_in[7];
    const float* bl2 = (const float*)d_in[8];
    const float* Wr2 = (const float*)d_in[9];
    // d_in[10..12] (Wlp, blp, Wrp) dead: softmax over a size-1 axis == 1
    const float* Wc1 = (const float*)d_in[13];
    const float* bc1 = (const float*)d_in[14];
    const float* Wc2 = (const float*)d_in[15];
    const float* bc2 = (const float*)d_in[16];
    float* out = (float*)d_out;

    dim3 mma_grid((NN + 127) / 128, 2, BAGS);    // (40, 2, 16)
    dim3 edge_grid((EE + 255) / 256, BAGS);

    k_zero<<<(BAGS * NN + 255) / 256, 256>>>();
    k_prep<<<(P_TOT + 255) / 256, 256>>>(x, ei, We, Wl1, Wr1, Wl2, Wr2);
    k_scan<<<BAGS, 1024>>>();
    k_fill<<<edge_grid, 256>>>(ei);
    // encoder
    k_enc<<<mma_grid, 256>>>(be);
    // layer 1
    k_layer<1, 2><<<mma_grid, 256>>>(bl1);
    k_agg2<false><<<(BAGS * NN) / 8, 256>>>();
    // layer 2
    k_layer<3, 4><<<mma_grid, 256>>>(bl2);
    k_agg2<true><<<(BAGS * NN) / 8, 256>>>();
    // pool + classify
    k_reduce<<<dim3(20, BAGS), 256>>>();
    k_cls<<<BAGS, 128>>>(Wc1, bc1, Wc2, bc2, out);
}